// round 10
// baseline (speedup 1.0000x reference)
#include <cuda_runtime.h>
#include <cuda_bf16.h>
#include <math.h>
#include <stdint.h>

// Problem constants
#define M_ROWS 4096   // B*S
#define DIM    1024   // H
#define SLEN   1024
#define NH     16
#define HD     64

// ---------------------------------------------------------------------------
// Scratch (allocation-free rule: __device__ globals)
// ---------------------------------------------------------------------------
__device__ __nv_bfloat16 g_x_hi[M_ROWS * DIM];
__device__ __nv_bfloat16 g_x_lo[M_ROWS * DIM];
__device__ __nv_bfloat16 g_q_hi[M_ROWS * DIM];
__device__ __nv_bfloat16 g_q_lo[M_ROWS * DIM];
__device__ __nv_bfloat16 g_k_hi[M_ROWS * DIM];
__device__ __nv_bfloat16 g_k_lo[M_ROWS * DIM];
__device__ __nv_bfloat16 g_v_hi[M_ROWS * DIM];
__device__ __nv_bfloat16 g_v_lo[M_ROWS * DIM];
__device__ __nv_bfloat16 g_vt_hi[M_ROWS * DIM];   // per-batch transposed V
__device__ __nv_bfloat16 g_vt_lo[M_ROWS * DIM];
__device__ __nv_bfloat16 g_a_hi[M_ROWS * DIM];    // attention output (split)
__device__ __nv_bfloat16 g_a_lo[M_ROWS * DIM];
__device__ __nv_bfloat16 g_wt_hi[4][DIM * DIM];   // transposed+split weights [N][K]
__device__ __nv_bfloat16 g_wt_lo[4][DIM * DIM];

// ---------------------------------------------------------------------------
// helpers
// ---------------------------------------------------------------------------
__device__ __forceinline__ uint32_t smem_u32(const void* p) {
    uint32_t a;
    asm("{ .reg .u64 t; cvta.to.shared.u64 t, %1; cvt.u32.u64 %0, t; }"
        : "=r"(a) : "l"(p));
    return a;
}
__device__ __forceinline__ void cp16(uint32_t dst, const void* src) {
    asm volatile("cp.async.cg.shared.global [%0], [%1], 16;"
                 :: "r"(dst), "l"(src));
}
__device__ __forceinline__ void cp_commit() {
    asm volatile("cp.async.commit_group;");
}
template <int N>
__device__ __forceinline__ void cp_wait() {
    asm volatile("cp.async.wait_group %0;" :: "n"(N));
}

__device__ __forceinline__ void mma_bf16(float* c, const uint32_t* a,
                                         const uint32_t* b) {
    asm volatile(
        "mma.sync.aligned.m16n8k16.row.col.f32.bf16.bf16.f32 "
        "{%0,%1,%2,%3}, {%4,%5,%6,%7}, {%8,%9}, {%0,%1,%2,%3};\n"
        : "+f"(c[0]), "+f"(c[1]), "+f"(c[2]), "+f"(c[3])
        : "r"(a[0]), "r"(a[1]), "r"(a[2]), "r"(a[3]), "r"(b[0]), "r"(b[1]));
}

__device__ __forceinline__ void ldsm4(uint32_t* r, uint32_t addr) {
    asm volatile(
        "ldmatrix.sync.aligned.m8n8.x4.shared.b16 {%0,%1,%2,%3}, [%4];"
        : "=r"(r[0]), "=r"(r[1]), "=r"(r[2]), "=r"(r[3]) : "r"(addr));
}

__device__ __forceinline__ uint32_t pack_bf16x2(float x, float y) {
    __nv_bfloat162 h = __floats2bfloat162_rn(x, y);
    return *reinterpret_cast<uint32_t*>(&h);
}
__device__ __forceinline__ float bf16_residual(float x) {
    return x - __bfloat162float(__float2bfloat16(x));
}

// ---------------------------------------------------------------------------
// Split: x (fp32) -> (hi, lo) bf16
// ---------------------------------------------------------------------------
__global__ void split_kernel(const float* __restrict__ in,
                             __nv_bfloat16* __restrict__ hi,
                             __nv_bfloat16* __restrict__ lo, int n4) {
    int i = blockIdx.x * blockDim.x + threadIdx.x;
    if (i >= n4) return;
    float4 x = reinterpret_cast<const float4*>(in)[i];
    uint32_t* hp = reinterpret_cast<uint32_t*>(hi);
    uint32_t* lp = reinterpret_cast<uint32_t*>(lo);
    hp[2 * i]     = pack_bf16x2(x.x, x.y);
    hp[2 * i + 1] = pack_bf16x2(x.z, x.w);
    lp[2 * i]     = pack_bf16x2(bf16_residual(x.x), bf16_residual(x.y));
    lp[2 * i + 1] = pack_bf16x2(bf16_residual(x.z), bf16_residual(x.w));
}

// ---------------------------------------------------------------------------
// Transpose + split: W[K][N] fp32 -> Wt_hi[N][K], Wt_lo[N][K] bf16
// ---------------------------------------------------------------------------
__global__ void transpose_split_kernel(const float* __restrict__ W,
                                       __nv_bfloat16* __restrict__ t_hi,
                                       __nv_bfloat16* __restrict__ t_lo) {
    __shared__ float tile[32][33];
    const int tx = threadIdx.x;
    const int ty = threadIdx.y;
    const int k0 = blockIdx.y * 32;
    const int n0 = blockIdx.x * 32;
#pragma unroll
    for (int i = 0; i < 4; i++)
        tile[ty + 8 * i][tx] = W[(size_t)(k0 + ty + 8 * i) * DIM + n0 + tx];
    __syncthreads();
#pragma unroll
    for (int i = 0; i < 4; i++) {
        float v = tile[tx][ty + 8 * i];
        size_t o = (size_t)(n0 + ty + 8 * i) * DIM + k0 + tx;
        t_hi[o] = __float2bfloat16(v);
        t_lo[o] = __float2bfloat16(bf16_residual(v));
    }
}

// ---------------------------------------------------------------------------
// Per-batch bf16 transpose: vt[b*1024 + col][s] = v[b*1024 + s][col]
// ---------------------------------------------------------------------------
__global__ void transpose_v_kernel(const __nv_bfloat16* __restrict__ vh,
                                   const __nv_bfloat16* __restrict__ vl,
                                   __nv_bfloat16* __restrict__ th,
                                   __nv_bfloat16* __restrict__ tl) {
    __shared__ __nv_bfloat16 tileh[32][33];
    __shared__ __nv_bfloat16 tilel[32][33];
    const int tx = threadIdx.x;
    const int ty = threadIdx.y;
    const int c0 = blockIdx.x * 32;
    const int s0 = blockIdx.y * 32;
    const int b  = blockIdx.z;
    const size_t base = (size_t)b * SLEN * DIM;
#pragma unroll
    for (int i = 0; i < 4; i++) {
        int s = s0 + ty + 8 * i;
        tileh[ty + 8 * i][tx] = vh[base + (size_t)s * DIM + c0 + tx];
        tilel[ty + 8 * i][tx] = vl[base + (size_t)s * DIM + c0 + tx];
    }
    __syncthreads();
#pragma unroll
    for (int i = 0; i < 4; i++) {
        int c = c0 + ty + 8 * i;
        th[base + (size_t)c * SLEN + s0 + tx] = tileh[tx][ty + 8 * i];
        tl[base + (size_t)c * SLEN + s0 + tx] = tilel[tx][ty + 8 * i];
    }
}

// ---------------------------------------------------------------------------
// bf16x3 tensor-core GEMM: C[4096,1024] = A @ W + bias
// ldmatrix.x4 fragment loads; 4-stage cp.async pipeline.
// OSPLIT=0: fp32 C out; OSPLIT=1: split bf16 (Chi, Clo) out.
// ---------------------------------------------------------------------------
#define BM 128
#define BN 128
#define BK 32
#define SH 40
#define SHB (SH * 2)                      // 80-byte smem row stride
#define MAT_BYTES (128 * SHB)
#define STAGE_BYTES (4 * MAT_BYTES)       // 40960
#define NSTAGE 4
#define GEMM_SMEM (NSTAGE * STAGE_BYTES)  // 163840
#define OFF_AHI 0
#define OFF_ALO MAT_BYTES
#define OFF_BHI (2 * MAT_BYTES)
#define OFF_BLO (3 * MAT_BYTES)

__device__ __forceinline__ void load_stage(uint32_t sdst,
                                           const __nv_bfloat16* __restrict__ A_hi,
                                           const __nv_bfloat16* __restrict__ A_lo,
                                           const __nv_bfloat16* __restrict__ B_hi,
                                           const __nv_bfloat16* __restrict__ B_lo,
                                           int rowBase, int colBase, int k0,
                                           int t) {
#pragma unroll
    for (int i = 0; i < 2; i++) {
        int id = t + 256 * i;
        int row = id >> 2;
        int c = id & 3;
        uint32_t soff = (uint32_t)(row * SHB + c * 16);
        const __nv_bfloat16* ah = A_hi + (size_t)(rowBase + row) * DIM + k0 + c * 8;
        const __nv_bfloat16* al = A_lo + (size_t)(rowBase + row) * DIM + k0 + c * 8;
        const __nv_bfloat16* bh = B_hi + (size_t)(colBase + row) * DIM + k0 + c * 8;
        const __nv_bfloat16* bl = B_lo + (size_t)(colBase + row) * DIM + k0 + c * 8;
        cp16(sdst + OFF_AHI + soff, ah);
        cp16(sdst + OFF_ALO + soff, al);
        cp16(sdst + OFF_BHI + soff, bh);
        cp16(sdst + OFF_BLO + soff, bl);
    }
    cp_commit();
}

template <int OSPLIT>
__global__ __launch_bounds__(256, 1)
void mma_gemm_kernel(const __nv_bfloat16* __restrict__ A_hi,
                     const __nv_bfloat16* __restrict__ A_lo,
                     const __nv_bfloat16* __restrict__ B_hi,
                     const __nv_bfloat16* __restrict__ B_lo,
                     const float* __restrict__ bias, float* __restrict__ C,
                     __nv_bfloat16* __restrict__ Chi,
                     __nv_bfloat16* __restrict__ Clo) {
    extern __shared__ __align__(128) unsigned char smem[];
    const uint32_t sbase = smem_u32(smem);

    const int t = threadIdx.x;
    const int lane = t & 31;
    const int wid = t >> 5;
    const int warp_m = wid & 3;
    const int warp_n = wid >> 2;
    const int group = lane >> 2;

    // per-lane ldmatrix offsets
    const int lr = lane & 7;
    const int lm = lane >> 3;                 // matrix index 0..3
    const int aRowOff = (warp_m * 32 + ((lm & 1) << 3) + lr) * SHB;
    const int aColOff = (lm >> 1) * 16;       // k+8 half
    const int bRowOff = (warp_n * 64 + ((lm >> 1) << 3) + lr) * SHB;
    const int bColOff = (lm & 1) * 16;

    const int rowBase = blockIdx.y * BM;
    const int colBase = blockIdx.x * BN;

    float acc[2][8][4];
#pragma unroll
    for (int f = 0; f < 2; f++)
#pragma unroll
        for (int g = 0; g < 8; g++)
#pragma unroll
            for (int r = 0; r < 4; r++) acc[f][g][r] = 0.0f;

#pragma unroll
    for (int s = 0; s < NSTAGE; s++)
        load_stage(sbase + s * STAGE_BYTES, A_hi, A_lo, B_hi, B_lo,
                   rowBase, colBase, s * BK, t);

    const int NCHUNK = DIM / BK;   // 32
    for (int c = 0; c < NCHUNK; c++) {
        if (c < NCHUNK - 3) cp_wait<3>();
        else if (c == NCHUNK - 3) cp_wait<2>();
        else if (c == NCHUNK - 2) cp_wait<1>();
        else cp_wait<0>();
        __syncthreads();

        const uint32_t stg = sbase + (uint32_t)((c % NSTAGE) * STAGE_BYTES);

#pragma unroll
        for (int ks = 0; ks < 2; ks++) {
            const int kcb = ks * 32;
            uint32_t ah[2][4], al[2][4], bh[8][2], bl[8][2];
#pragma unroll
            for (int f = 0; f < 2; f++) {
                uint32_t aoff = (uint32_t)(aRowOff + f * 16 * SHB + kcb + aColOff);
                ldsm4(ah[f], stg + OFF_AHI + aoff);
                ldsm4(al[f], stg + OFF_ALO + aoff);
            }
#pragma unroll
            for (int gp = 0; gp < 4; gp++) {
                uint32_t boff = (uint32_t)(bRowOff + gp * 16 * SHB + kcb + bColOff);
                ldsm4(&bh[2 * gp][0], stg + OFF_BHI + boff);
                ldsm4(&bl[2 * gp][0], stg + OFF_BLO + boff);
            }
#pragma unroll
            for (int f = 0; f < 2; f++)
#pragma unroll
                for (int g = 0; g < 8; g++) {
                    mma_bf16(acc[f][g], ah[f], bh[g]);
                    mma_bf16(acc[f][g], ah[f], bl[g]);
                    mma_bf16(acc[f][g], al[f], bh[g]);
                }
        }
        __syncthreads();

        if (c + NSTAGE < NCHUNK)
            load_stage(sbase + (c % NSTAGE) * STAGE_BYTES, A_hi, A_lo, B_hi,
                       B_lo, rowBase, colBase, (c + NSTAGE) * BK, t);
    }

#pragma unroll
    for (int g = 0; g < 8; g++) {
        int col0 = colBase + warp_n * 64 + g * 8 + (lane & 3) * 2;
        float2 bb = *reinterpret_cast<const float2*>(&bias[col0]);
#pragma unroll
        for (int f = 0; f < 2; f++) {
            int r0 = rowBase + warp_m * 32 + f * 16 + group;
            float v0 = acc[f][g][0] + bb.x, v1 = acc[f][g][1] + bb.y;
            float v2 = acc[f][g][2] + bb.x, v3 = acc[f][g][3] + bb.y;
            if (OSPLIT) {
                *reinterpret_cast<uint32_t*>(&Chi[(size_t)r0 * DIM + col0]) =
                    pack_bf16x2(v0, v1);
                *reinterpret_cast<uint32_t*>(&Clo[(size_t)r0 * DIM + col0]) =
                    pack_bf16x2(bf16_residual(v0), bf16_residual(v1));
                *reinterpret_cast<uint32_t*>(&Chi[(size_t)(r0 + 8) * DIM + col0]) =
                    pack_bf16x2(v2, v3);
                *reinterpret_cast<uint32_t*>(&Clo[(size_t)(r0 + 8) * DIM + col0]) =
                    pack_bf16x2(bf16_residual(v2), bf16_residual(v3));
            } else {
                *reinterpret_cast<float2*>(&C[(size_t)r0 * DIM + col0]) =
                    make_float2(v0, v1);
                *reinterpret_cast<float2*>(&C[(size_t)(r0 + 8) * DIM + col0]) =
                    make_float2(v2, v3);
            }
        }
    }
}

// ---------------------------------------------------------------------------
// Tensor-core flash attention, register-resident P (unchanged from R8 WIN)
// ---------------------------------------------------------------------------
#define ATQ 128
#define ATK 64
#define ASHB 144                        // smem row stride bytes (72 bf16)
#define AQ_H 0
#define AQ_L (ATQ * ASHB)               // 18432
#define AST0 (2 * ATQ * ASHB)           // 36864
#define ASTAGE_BYTES (4 * ATK * ASHB)   // 36864 (kh,kl,vth,vtl)
#define AK_H 0
#define AK_L (ATK * ASHB)
#define AV_H (2 * ATK * ASHB)
#define AV_L (3 * ATK * ASHB)
#define AMSK (AST0 + 2 * ASTAGE_BYTES)  // 110592, 2 x 64 floats
#define ATTN_SMEM (AMSK + 2 * 256)      // 111104

__device__ __forceinline__ void attn_load_stage(
    uint32_t sbase,
    const __nv_bfloat16* kh, const __nv_bfloat16* kl,
    const __nv_bfloat16* vth, const __nv_bfloat16* vtl,
    const unsigned char* mk,
    int b, int hcol, int kb, int t) {
    const uint32_t sdst = sbase + AST0 + (uint32_t)(kb & 1) * ASTAGE_BYTES;
    const uint32_t smsk = sbase + AMSK + (uint32_t)(kb & 1) * 256;
    const int keyBase = b * SLEN + kb * ATK;
    const int vtBase  = b * SLEN + hcol;
    const int vtCol   = kb * ATK;
#pragma unroll
    for (int i = 0; i < 2; i++) {
        int id = t + 256 * i;
        int row = id >> 3;
        int c = id & 7;
        uint32_t soff = (uint32_t)(row * ASHB + c * 16);
        cp16(sdst + AK_H + soff,
             kh + (size_t)(keyBase + row) * DIM + hcol + c * 8);
        cp16(sdst + AK_L + soff,
             kl + (size_t)(keyBase + row) * DIM + hcol + c * 8);
        cp16(sdst + AV_H + soff,
             vth + (size_t)(vtBase + row) * SLEN + vtCol + c * 8);
        cp16(sdst + AV_L + soff,
             vtl + (size_t)(vtBase + row) * SLEN + vtCol + c * 8);
    }
    if (t < ATK) {
        float add = mk[b * SLEN + kb * ATK + t] ? -1e30f : 0.0f;
        asm volatile("st.shared.f32 [%0], %1;" :: "r"(smsk + t * 4), "f"(add));
    }
    cp_commit();
}

__global__ __launch_bounds__(256, 2)
void attn_mma_kernel(const __nv_bfloat16* __restrict__ qh,
                     const __nv_bfloat16* __restrict__ ql,
                     const __nv_bfloat16* __restrict__ kh,
                     const __nv_bfloat16* __restrict__ kl,
                     const __nv_bfloat16* __restrict__ vth,
                     const __nv_bfloat16* __restrict__ vtl,
                     const unsigned char* __restrict__ mk,
                     __nv_bfloat16* __restrict__ Oh,
                     __nv_bfloat16* __restrict__ Ol) {
    extern __shared__ __align__(128) unsigned char smem[];
    const uint32_t sbase = smem_u32(smem);

    const int t = threadIdx.x;
    const int lane = t & 31;
    const int w = t >> 5;
    const int group = lane >> 2;
    const int tc4 = (lane & 3) * 4;

    const int qb = blockIdx.x;
    const int h  = blockIdx.y;
    const int b  = blockIdx.z;
    const int qBase = b * SLEN + qb * ATQ;
    const int hcol  = h * HD;

    const float qscale = 0.125f * 1.44269504088896340736f;

#pragma unroll
    for (int i = 0; i < 4; i++) {
        int id = t + 256 * i;
        int row = id >> 3;
        int c = id & 7;
        uint32_t soff = (uint32_t)(row * ASHB + c * 16);
        cp16(sbase + AQ_H + soff, qh + (size_t)(qBase + row) * DIM + hcol + c * 8);
        cp16(sbase + AQ_L + soff, ql + (size_t)(qBase + row) * DIM + hcol + c * 8);
    }
    cp_commit();
    attn_load_stage(sbase, kh, kl, vth, vtl, mk, b, hcol, 0, t);
    attn_load_stage(sbase, kh, kl, vth, vtl, mk, b, hcol, 1, t);

    float o[8][4];
    float m_i[2], l_i[2];
#pragma unroll
    for (int g = 0; g < 8; g++)
#pragma unroll
        for (int r = 0; r < 4; r++) o[g][r] = 0.0f;
    m_i[0] = m_i[1] = -1e30f;
    l_i[0] = l_i[1] = 0.0f;

    const int NT = SLEN / ATK;   // 16
    for (int kb = 0; kb < NT; kb++) {
        if (kb == NT - 1) cp_wait<0>(); else cp_wait<1>();
        __syncthreads();

        const unsigned char* stg = smem + AST0 + (kb & 1) * ASTAGE_BYTES;
        const unsigned char* pKh = stg + AK_H;
        const unsigned char* pKl = stg + AK_L;
        const unsigned char* pVh = stg + AV_H;
        const unsigned char* pVl = stg + AV_L;
        const float* madd =
            reinterpret_cast<const float*>(smem + AMSK + (kb & 1) * 256);

        float s[8][4];
#pragma unroll
        for (int g = 0; g < 8; g++)
#pragma unroll
            for (int r = 0; r < 4; r++) s[g][r] = 0.0f;

        const unsigned char* pQh = smem + AQ_H;
        const unsigned char* pQl = smem + AQ_L;
#pragma unroll
        for (int k = 0; k < 4; k++) {
            const int cb = tc4 + k * 32;
            uint32_t ah[4], al[4];
            int abase = (w * 16 + group) * ASHB + cb;
            ah[0] = *(const uint32_t*)(pQh + abase);
            ah[1] = *(const uint32_t*)(pQh + abase + 8 * ASHB);
            ah[2] = *(const uint32_t*)(pQh + abase + 16);
            ah[3] = *(const uint32_t*)(pQh + abase + 8 * ASHB + 16);
            al[0] = *(const uint32_t*)(pQl + abase);
            al[1] = *(const uint32_t*)(pQl + abase + 8 * ASHB);
            al[2] = *(const uint32_t*)(pQl + abase + 16);
            al[3] = *(const uint32_t*)(pQl + abase + 8 * ASHB + 16);
#pragma unroll
            for (int g = 0; g < 8; g++) {
                int bbase = (g * 8 + group) * ASHB + cb;
                uint32_t bh[2], bl[2];
                bh[0] = *(const uint32_t*)(pKh + bbase);
                bh[1] = *(const uint32_t*)(pKh + bbase + 16);
                bl[0] = *(const uint32_t*)(pKl + bbase);
                bl[1] = *(const uint32_t*)(pKl + bbase + 16);
                mma_bf16(s[g], ah, bh);
                mma_bf16(s[g], ah, bl);
                mma_bf16(s[g], al, bh);
            }
        }

#pragma unroll
        for (int g = 0; g < 8; g++) {
            float2 ma = *reinterpret_cast<const float2*>(
                &madd[g * 8 + (lane & 3) * 2]);
            s[g][0] = fmaf(s[g][0], qscale, ma.x);
            s[g][1] = fmaf(s[g][1], qscale, ma.y);
            s[g][2] = fmaf(s[g][2], qscale, ma.x);
            s[g][3] = fmaf(s[g][3], qscale, ma.y);
        }
        float mx0 = -1e30f, mx1 = -1e30f;
#pragma unroll
        for (int g = 0; g < 8; g++) {
            mx0 = fmaxf(mx0, fmaxf(s[g][0], s[g][1]));
            mx1 = fmaxf(mx1, fmaxf(s[g][2], s[g][3]));
        }
        mx0 = fmaxf(mx0, __shfl_xor_sync(0xffffffffu, mx0, 1));
        mx0 = fmaxf(mx0, __shfl_xor_sync(0xffffffffu, mx0, 2));
        mx1 = fmaxf(mx1, __shfl_xor_sync(0xffffffffu, mx1, 1));
        mx1 = fmaxf(mx1, __shfl_xor_sync(0xffffffffu, mx1, 2));
        float mn0 = fmaxf(m_i[0], mx0);
        float mn1 = fmaxf(m_i[1], mx1);
        float corr0 = exp2f(m_i[0] - mn0);
        float corr1 = exp2f(m_i[1] - mn1);
        m_i[0] = mn0; m_i[1] = mn1;

        uint32_t pah[4][4], pal[4][4];
        float sum0 = 0.0f, sum1 = 0.0f;
#pragma unroll
        for (int g = 0; g < 8; g++) {
            float p0 = exp2f(s[g][0] - mn0);
            float p1 = exp2f(s[g][1] - mn0);
            float p2 = exp2f(s[g][2] - mn1);
            float p3 = exp2f(s[g][3] - mn1);
            sum0 += p0 + p1;
            sum1 += p2 + p3;
            const int kc = g >> 1;
            const int o2 = (g & 1) * 2;
            pah[kc][o2 + 0] = pack_bf16x2(p0, p1);
            pah[kc][o2 + 1] = pack_bf16x2(p2, p3);
            pal[kc][o2 + 0] = pack_bf16x2(bf16_residual(p0), bf16_residual(p1));
            pal[kc][o2 + 1] = pack_bf16x2(bf16_residual(p2), bf16_residual(p3));
        }
        sum0 += __shfl_xor_sync(0xffffffffu, sum0, 1);
        sum0 += __shfl_xor_sync(0xffffffffu, sum0, 2);
        sum1 += __shfl_xor_sync(0xffffffffu, sum1, 1);
        sum1 += __shfl_xor_sync(0xffffffffu, sum1, 2);
        l_i[0] = l_i[0] * corr0 + sum0;
        l_i[1] = l_i[1] * corr1 + sum1;
#pragma unroll
        for (int g = 0; g < 8; g++) {
            o[g][0] *= corr0; o[g][1] *= corr0;
            o[g][2] *= corr1; o[g][3] *= corr1;
        }

#pragma unroll
        for (int kc = 0; kc < 4; kc++) {
            const int cb = tc4 + kc * 32;
#pragma unroll
            for (int d = 0; d < 8; d++) {
                int bbase = (d * 8 + group) * ASHB + cb;
                uint32_t bh[2], bl[2];
                bh[0] = *(const uint32_t*)(pVh + bbase);
                bh[1] = *(const uint32_t*)(pVh + bbase + 16);
                bl[0] = *(const uint32_t*)(pVl + bbase);
                bl[1] = *(const uint32_t*)(pVl + bbase + 16);
                mma_bf16(o[d], pah[kc], bh);
                mma_bf16(o[d], pah[kc], bl);
                mma_bf16(o[d], pal[kc], bh);
            }
        }
        __syncthreads();

        if (kb + 2 < NT)
            attn_load_stage(sbase, kh, kl, vth, vtl, mk, b, hcol, kb + 2, t);
    }

    float inv0 = 1.0f / l_i[0];
    float inv1 = 1.0f / l_i[1];
    const int gr0 = qBase + w * 16 + group;
#pragma unroll
    for (int g = 0; g < 8; g++) {
        int col = hcol + g * 8 + (lane & 3) * 2;
        float v0 = o[g][0] * inv0, v1 = o[g][1] * inv0;
        float v2 = o[g][2] * inv1, v3 = o[g][3] * inv1;
        *reinterpret_cast<uint32_t*>(&Oh[(size_t)gr0 * DIM + col]) =
            pack_bf16x2(v0, v1);
        *reinterpret_cast<uint32_t*>(&Ol[(size_t)gr0 * DIM + col]) =
            pack_bf16x2(bf16_residual(v0), bf16_residual(v1));
        *reinterpret_cast<uint32_t*>(&Oh[(size_t)(gr0 + 8) * DIM + col]) =
            pack_bf16x2(v2, v3);
        *reinterpret_cast<uint32_t*>(&Ol[(size_t)(gr0 + 8) * DIM + col]) =
            pack_bf16x2(bf16_residual(v2), bf16_residual(v3));
    }
}

// ---------------------------------------------------------------------------
// Launcher. Launch order is chosen so the ncu capture slot (~user launch
// idx 4) lands on the Q-projection GEMM instead of a prep kernel:
//   0: t0  1: t1  2: t2  3: split  4: gemmQ  5: t3  6: gemmK  7: gemmV
//   8: transpose_v  9: attn  10: gemmO
// ---------------------------------------------------------------------------
extern "C" void kernel_launch(void* const* d_in, const int* in_sizes, int n_in,
                              void* d_out, int out_size) {
    (void)in_sizes; (void)n_in; (void)out_size;
    const float* x          = (const float*)d_in[0];
    const unsigned char* mk = (const unsigned char*)d_in[1];
    const float* w[4] = {(const float*)d_in[2], (const float*)d_in[4],
                         (const float*)d_in[6], (const float*)d_in[8]};
    const float* bq = (const float*)d_in[3];
    const float* bk = (const float*)d_in[5];
    const float* bv = (const float*)d_in[7];
    const float* bo = (const float*)d_in[9];
    float* out = (float*)d_out;

    __nv_bfloat16 *xh, *xl, *qhp, *qlp, *khp, *klp, *vhp, *vlp;
    __nv_bfloat16 *vth, *vtl, *ah, *al, *wth, *wtl;
    cudaGetSymbolAddress((void**)&xh, g_x_hi);
    cudaGetSymbolAddress((void**)&xl, g_x_lo);
    cudaGetSymbolAddress((void**)&qhp, g_q_hi);
    cudaGetSymbolAddress((void**)&qlp, g_q_lo);
    cudaGetSymbolAddress((void**)&khp, g_k_hi);
    cudaGetSymbolAddress((void**)&klp, g_k_lo);
    cudaGetSymbolAddress((void**)&vhp, g_v_hi);
    cudaGetSymbolAddress((void**)&vlp, g_v_lo);
    cudaGetSymbolAddress((void**)&vth, g_vt_hi);
    cudaGetSymbolAddress((void**)&vtl, g_vt_lo);
    cudaGetSymbolAddress((void**)&ah, g_a_hi);
    cudaGetSymbolAddress((void**)&al, g_a_lo);
    cudaGetSymbolAddress((void**)&wth, g_wt_hi);
    cudaGetSymbolAddress((void**)&wtl, g_wt_lo);

    const int n4 = M_ROWS * DIM / 4;
    dim3 tgrid(DIM / 32, DIM / 32);

    cudaFuncSetAttribute(mma_gemm_kernel<0>,
                         cudaFuncAttributeMaxDynamicSharedMemorySize, GEMM_SMEM);
    cudaFuncSetAttribute(mma_gemm_kernel<1>,
                         cudaFuncAttributeMaxDynamicSharedMemorySize, GEMM_SMEM);
    cudaFuncSetAttribute(attn_mma_kernel,
                         cudaFuncAttributeMaxDynamicSharedMemorySize, ATTN_SMEM);
    dim3 ggrid(DIM / BN, M_ROWS / BM);

    // idx 0..2: Q/K/V weight transposes
    for (int i = 0; i < 3; i++)
        transpose_split_kernel<<<tgrid, dim3(32, 8)>>>(
            w[i], wth + (size_t)i * DIM * DIM, wtl + (size_t)i * DIM * DIM);
    // idx 3: x split
    split_kernel<<<(n4 + 255) / 256, 256>>>(x, xh, xl, n4);
    // idx 4: Q GEMM  <-- ncu capture target
    mma_gemm_kernel<1><<<ggrid, 256, GEMM_SMEM>>>(
        xh, xl, wth + 0 * (size_t)DIM * DIM, wtl + 0 * (size_t)DIM * DIM, bq,
        nullptr, qhp, qlp);
    // idx 5: output-weight transpose
    transpose_split_kernel<<<tgrid, dim3(32, 8)>>>(
        w[3], wth + 3 * (size_t)DIM * DIM, wtl + 3 * (size_t)DIM * DIM);
    // idx 6,7: K and V GEMMs
    mma_gemm_kernel<1><<<ggrid, 256, GEMM_SMEM>>>(
        xh, xl, wth + 1 * (size_t)DIM * DIM, wtl + 1 * (size_t)DIM * DIM, bk,
        nullptr, khp, klp);
    mma_gemm_kernel<1><<<ggrid, 256, GEMM_SMEM>>>(
        xh, xl, wth + 2 * (size_t)DIM * DIM, wtl + 2 * (size_t)DIM * DIM, bv,
        nullptr, vhp, vlp);
    // idx 8: V transpose
    transpose_v_kernel<<<dim3(32, 32, 4), dim3(32, 8)>>>(vhp, vlp, vth, vtl);
    // idx 9: attention
    attn_mma_kernel<<<dim3(SLEN / ATQ, NH, 4), 256, ATTN_SMEM>>>(
        qhp, qlp, khp, klp, vth, vtl, mk, ah, al);
    // idx 10: output GEMM
    mma_gemm_kernel<0><<<ggrid, 256, GEMM_SMEM>>>(
        ah, al, wth + 3 * (size_t)DIM * DIM, wtl + 3 * (size_t)DIM * DIM, bo,
        out, nullptr, nullptr);
}

// round 11
// speedup vs baseline: 1.0132x; 1.0132x over previous
#include <cuda_runtime.h>
#include <cuda_bf16.h>
#include <math.h>
#include <stdint.h>

// Problem constants
#define M_ROWS 4096   // B*S
#define DIM    1024   // H
#define SLEN   1024
#define NH     16
#define HD     64

// ---------------------------------------------------------------------------
// Scratch (allocation-free rule: __device__ globals)
// ---------------------------------------------------------------------------
__device__ __nv_bfloat16 g_x_hi[M_ROWS * DIM];
__device__ __nv_bfloat16 g_x_lo[M_ROWS * DIM];
__device__ __nv_bfloat16 g_q_hi[M_ROWS * DIM];
__device__ __nv_bfloat16 g_q_lo[M_ROWS * DIM];
__device__ __nv_bfloat16 g_k_hi[M_ROWS * DIM];
__device__ __nv_bfloat16 g_k_lo[M_ROWS * DIM];
__device__ __nv_bfloat16 g_v_hi[M_ROWS * DIM];
__device__ __nv_bfloat16 g_v_lo[M_ROWS * DIM];
__device__ __nv_bfloat16 g_vt_hi[M_ROWS * DIM];   // per-batch transposed V
__device__ __nv_bfloat16 g_vt_lo[M_ROWS * DIM];
__device__ __nv_bfloat16 g_a_hi[M_ROWS * DIM];    // attention output (split)
__device__ __nv_bfloat16 g_a_lo[M_ROWS * DIM];
__device__ __nv_bfloat16 g_wt_hi[4][DIM * DIM];   // transposed+split weights [N][K]
__device__ __nv_bfloat16 g_wt_lo[4][DIM * DIM];

// ---------------------------------------------------------------------------
// helpers
// ---------------------------------------------------------------------------
__device__ __forceinline__ uint32_t smem_u32(const void* p) {
    uint32_t a;
    asm("{ .reg .u64 t; cvta.to.shared.u64 t, %1; cvt.u32.u64 %0, t; }"
        : "=r"(a) : "l"(p));
    return a;
}
__device__ __forceinline__ void cp16(uint32_t dst, const void* src) {
    asm volatile("cp.async.cg.shared.global [%0], [%1], 16;"
                 :: "r"(dst), "l"(src));
}
__device__ __forceinline__ void cp_commit() {
    asm volatile("cp.async.commit_group;");
}
template <int N>
__device__ __forceinline__ void cp_wait() {
    asm volatile("cp.async.wait_group %0;" :: "n"(N));
}

__device__ __forceinline__ void mma_bf16(float* c, const uint32_t* a,
                                         const uint32_t* b) {
    asm volatile(
        "mma.sync.aligned.m16n8k16.row.col.f32.bf16.bf16.f32 "
        "{%0,%1,%2,%3}, {%4,%5,%6,%7}, {%8,%9}, {%0,%1,%2,%3};\n"
        : "+f"(c[0]), "+f"(c[1]), "+f"(c[2]), "+f"(c[3])
        : "r"(a[0]), "r"(a[1]), "r"(a[2]), "r"(a[3]), "r"(b[0]), "r"(b[1]));
}

__device__ __forceinline__ void ldsm4(uint32_t* r, uint32_t addr) {
    asm volatile(
        "ldmatrix.sync.aligned.m8n8.x4.shared.b16 {%0,%1,%2,%3}, [%4];"
        : "=r"(r[0]), "=r"(r[1]), "=r"(r[2]), "=r"(r[3]) : "r"(addr));
}

__device__ __forceinline__ uint32_t pack_bf16x2(float x, float y) {
    __nv_bfloat162 h = __floats2bfloat162_rn(x, y);
    return *reinterpret_cast<uint32_t*>(&h);
}
__device__ __forceinline__ float bf16_residual(float x) {
    return x - __bfloat162float(__float2bfloat16(x));
}

// ---------------------------------------------------------------------------
// Split: x (fp32) -> (hi, lo) bf16
// ---------------------------------------------------------------------------
__global__ void split_kernel(const float* __restrict__ in,
                             __nv_bfloat16* __restrict__ hi,
                             __nv_bfloat16* __restrict__ lo, int n4) {
    int i = blockIdx.x * blockDim.x + threadIdx.x;
    if (i >= n4) return;
    float4 x = reinterpret_cast<const float4*>(in)[i];
    uint32_t* hp = reinterpret_cast<uint32_t*>(hi);
    uint32_t* lp = reinterpret_cast<uint32_t*>(lo);
    hp[2 * i]     = pack_bf16x2(x.x, x.y);
    hp[2 * i + 1] = pack_bf16x2(x.z, x.w);
    lp[2 * i]     = pack_bf16x2(bf16_residual(x.x), bf16_residual(x.y));
    lp[2 * i + 1] = pack_bf16x2(bf16_residual(x.z), bf16_residual(x.w));
}

// ---------------------------------------------------------------------------
// Transpose + split: W[K][N] fp32 -> Wt_hi[N][K], Wt_lo[N][K] bf16
// ---------------------------------------------------------------------------
__global__ void transpose_split_kernel(const float* __restrict__ W,
                                       __nv_bfloat16* __restrict__ t_hi,
                                       __nv_bfloat16* __restrict__ t_lo) {
    __shared__ float tile[32][33];
    const int tx = threadIdx.x;
    const int ty = threadIdx.y;
    const int k0 = blockIdx.y * 32;
    const int n0 = blockIdx.x * 32;
#pragma unroll
    for (int i = 0; i < 4; i++)
        tile[ty + 8 * i][tx] = W[(size_t)(k0 + ty + 8 * i) * DIM + n0 + tx];
    __syncthreads();
#pragma unroll
    for (int i = 0; i < 4; i++) {
        float v = tile[tx][ty + 8 * i];
        size_t o = (size_t)(n0 + ty + 8 * i) * DIM + k0 + tx;
        t_hi[o] = __float2bfloat16(v);
        t_lo[o] = __float2bfloat16(bf16_residual(v));
    }
}

// ---------------------------------------------------------------------------
// Per-batch bf16 transpose: vt[b*1024 + col][s] = v[b*1024 + s][col]
// ---------------------------------------------------------------------------
__global__ void transpose_v_kernel(const __nv_bfloat16* __restrict__ vh,
                                   const __nv_bfloat16* __restrict__ vl,
                                   __nv_bfloat16* __restrict__ th,
                                   __nv_bfloat16* __restrict__ tl) {
    __shared__ __nv_bfloat16 tileh[32][33];
    __shared__ __nv_bfloat16 tilel[32][33];
    const int tx = threadIdx.x;
    const int ty = threadIdx.y;
    const int c0 = blockIdx.x * 32;
    const int s0 = blockIdx.y * 32;
    const int b  = blockIdx.z;
    const size_t base = (size_t)b * SLEN * DIM;
#pragma unroll
    for (int i = 0; i < 4; i++) {
        int s = s0 + ty + 8 * i;
        tileh[ty + 8 * i][tx] = vh[base + (size_t)s * DIM + c0 + tx];
        tilel[ty + 8 * i][tx] = vl[base + (size_t)s * DIM + c0 + tx];
    }
    __syncthreads();
#pragma unroll
    for (int i = 0; i < 4; i++) {
        int c = c0 + ty + 8 * i;
        th[base + (size_t)c * SLEN + s0 + tx] = tileh[tx][ty + 8 * i];
        tl[base + (size_t)c * SLEN + s0 + tx] = tilel[tx][ty + 8 * i];
    }
}

// ---------------------------------------------------------------------------
// bf16x3 tensor-core GEMM: C[4096,1024] = A @ W + bias
// ldmatrix.x4 fragment loads; 3-stage cp.async pipeline.
// OSPLIT=0: fp32 C out; OSPLIT=1: split bf16 (Chi, Clo) out.
// ---------------------------------------------------------------------------
#define BM 128
#define BN 128
#define BK 32
#define SH 40
#define SHB (SH * 2)                      // 80-byte smem row stride
#define MAT_BYTES (128 * SHB)
#define STAGE_BYTES (4 * MAT_BYTES)       // 40960
#define NSTAGE 3
#define GEMM_SMEM (NSTAGE * STAGE_BYTES)  // 122880
#define OFF_AHI 0
#define OFF_ALO MAT_BYTES
#define OFF_BHI (2 * MAT_BYTES)
#define OFF_BLO (3 * MAT_BYTES)

__device__ __forceinline__ void load_stage(uint32_t sdst,
                                           const __nv_bfloat16* __restrict__ A_hi,
                                           const __nv_bfloat16* __restrict__ A_lo,
                                           const __nv_bfloat16* __restrict__ B_hi,
                                           const __nv_bfloat16* __restrict__ B_lo,
                                           int rowBase, int colBase, int k0,
                                           int t) {
#pragma unroll
    for (int i = 0; i < 2; i++) {
        int id = t + 256 * i;
        int row = id >> 2;
        int c = id & 3;
        uint32_t soff = (uint32_t)(row * SHB + c * 16);
        const __nv_bfloat16* ah = A_hi + (size_t)(rowBase + row) * DIM + k0 + c * 8;
        const __nv_bfloat16* al = A_lo + (size_t)(rowBase + row) * DIM + k0 + c * 8;
        const __nv_bfloat16* bh = B_hi + (size_t)(colBase + row) * DIM + k0 + c * 8;
        const __nv_bfloat16* bl = B_lo + (size_t)(colBase + row) * DIM + k0 + c * 8;
        cp16(sdst + OFF_AHI + soff, ah);
        cp16(sdst + OFF_ALO + soff, al);
        cp16(sdst + OFF_BHI + soff, bh);
        cp16(sdst + OFF_BLO + soff, bl);
    }
    cp_commit();
}

template <int OSPLIT>
__global__ __launch_bounds__(256, 1)
void mma_gemm_kernel(const __nv_bfloat16* __restrict__ A_hi,
                     const __nv_bfloat16* __restrict__ A_lo,
                     const __nv_bfloat16* __restrict__ B_hi,
                     const __nv_bfloat16* __restrict__ B_lo,
                     const float* __restrict__ bias, float* __restrict__ C,
                     __nv_bfloat16* __restrict__ Chi,
                     __nv_bfloat16* __restrict__ Clo) {
    extern __shared__ __align__(128) unsigned char smem[];
    const uint32_t sbase = smem_u32(smem);

    const int t = threadIdx.x;
    const int lane = t & 31;
    const int wid = t >> 5;
    const int warp_m = wid & 3;
    const int warp_n = wid >> 2;
    const int group = lane >> 2;

    // per-lane ldmatrix offsets
    const int lr = lane & 7;
    const int lm = lane >> 3;                 // matrix index 0..3
    const int aRowOff = (warp_m * 32 + ((lm & 1) << 3) + lr) * SHB;
    const int aColOff = (lm >> 1) * 16;       // k+8 half
    const int bRowOff = (warp_n * 64 + ((lm >> 1) << 3) + lr) * SHB;
    const int bColOff = (lm & 1) * 16;

    const int rowBase = blockIdx.y * BM;
    const int colBase = blockIdx.x * BN;

    float acc[2][8][4];
#pragma unroll
    for (int f = 0; f < 2; f++)
#pragma unroll
        for (int g = 0; g < 8; g++)
#pragma unroll
            for (int r = 0; r < 4; r++) acc[f][g][r] = 0.0f;

#pragma unroll
    for (int s = 0; s < NSTAGE; s++)
        load_stage(sbase + s * STAGE_BYTES, A_hi, A_lo, B_hi, B_lo,
                   rowBase, colBase, s * BK, t);

    const int NCHUNK = DIM / BK;   // 32
    for (int c = 0; c < NCHUNK; c++) {
        if (c < NCHUNK - 2) cp_wait<2>();
        else if (c == NCHUNK - 2) cp_wait<1>();
        else cp_wait<0>();
        __syncthreads();

        const uint32_t stg = sbase + (uint32_t)((c % NSTAGE) * STAGE_BYTES);

#pragma unroll
        for (int ks = 0; ks < 2; ks++) {
            const int kcb = ks * 32;
            uint32_t ah[2][4], al[2][4], bh[8][2], bl[8][2];
#pragma unroll
            for (int f = 0; f < 2; f++) {
                uint32_t aoff = (uint32_t)(aRowOff + f * 16 * SHB + kcb + aColOff);
                ldsm4(ah[f], stg + OFF_AHI + aoff);
                ldsm4(al[f], stg + OFF_ALO + aoff);
            }
#pragma unroll
            for (int gp = 0; gp < 4; gp++) {
                uint32_t boff = (uint32_t)(bRowOff + gp * 16 * SHB + kcb + bColOff);
                ldsm4(&bh[2 * gp][0], stg + OFF_BHI + boff);
                ldsm4(&bl[2 * gp][0], stg + OFF_BLO + boff);
            }
#pragma unroll
            for (int f = 0; f < 2; f++)
#pragma unroll
                for (int g = 0; g < 8; g++) {
                    mma_bf16(acc[f][g], ah[f], bh[g]);
                    mma_bf16(acc[f][g], ah[f], bl[g]);
                    mma_bf16(acc[f][g], al[f], bh[g]);
                }
        }
        __syncthreads();

        if (c + NSTAGE < NCHUNK)
            load_stage(sbase + (c % NSTAGE) * STAGE_BYTES, A_hi, A_lo, B_hi,
                       B_lo, rowBase, colBase, (c + NSTAGE) * BK, t);
    }

#pragma unroll
    for (int g = 0; g < 8; g++) {
        int col0 = colBase + warp_n * 64 + g * 8 + (lane & 3) * 2;
        float2 bb = *reinterpret_cast<const float2*>(&bias[col0]);
#pragma unroll
        for (int f = 0; f < 2; f++) {
            int r0 = rowBase + warp_m * 32 + f * 16 + group;
            float v0 = acc[f][g][0] + bb.x, v1 = acc[f][g][1] + bb.y;
            float v2 = acc[f][g][2] + bb.x, v3 = acc[f][g][3] + bb.y;
            if (OSPLIT) {
                *reinterpret_cast<uint32_t*>(&Chi[(size_t)r0 * DIM + col0]) =
                    pack_bf16x2(v0, v1);
                *reinterpret_cast<uint32_t*>(&Clo[(size_t)r0 * DIM + col0]) =
                    pack_bf16x2(bf16_residual(v0), bf16_residual(v1));
                *reinterpret_cast<uint32_t*>(&Chi[(size_t)(r0 + 8) * DIM + col0]) =
                    pack_bf16x2(v2, v3);
                *reinterpret_cast<uint32_t*>(&Clo[(size_t)(r0 + 8) * DIM + col0]) =
                    pack_bf16x2(bf16_residual(v2), bf16_residual(v3));
            } else {
                *reinterpret_cast<float2*>(&C[(size_t)r0 * DIM + col0]) =
                    make_float2(v0, v1);
                *reinterpret_cast<float2*>(&C[(size_t)(r0 + 8) * DIM + col0]) =
                    make_float2(v2, v3);
            }
        }
    }
}

// ---------------------------------------------------------------------------
// Tensor-core flash attention, register-resident P (unchanged from R8 WIN)
// ---------------------------------------------------------------------------
#define ATQ 128
#define ATK 64
#define ASHB 144                        // smem row stride bytes (72 bf16)
#define AQ_H 0
#define AQ_L (ATQ * ASHB)               // 18432
#define AST0 (2 * ATQ * ASHB)           // 36864
#define ASTAGE_BYTES (4 * ATK * ASHB)   // 36864 (kh,kl,vth,vtl)
#define AK_H 0
#define AK_L (ATK * ASHB)
#define AV_H (2 * ATK * ASHB)
#define AV_L (3 * ATK * ASHB)
#define AMSK (AST0 + 2 * ASTAGE_BYTES)  // 110592, 2 x 64 floats
#define ATTN_SMEM (AMSK + 2 * 256)      // 111104

__device__ __forceinline__ void attn_load_stage(
    uint32_t sbase,
    const __nv_bfloat16* kh, const __nv_bfloat16* kl,
    const __nv_bfloat16* vth, const __nv_bfloat16* vtl,
    const unsigned char* mk,
    int b, int hcol, int kb, int t) {
    const uint32_t sdst = sbase + AST0 + (uint32_t)(kb & 1) * ASTAGE_BYTES;
    const uint32_t smsk = sbase + AMSK + (uint32_t)(kb & 1) * 256;
    const int keyBase = b * SLEN + kb * ATK;
    const int vtBase  = b * SLEN + hcol;
    const int vtCol   = kb * ATK;
#pragma unroll
    for (int i = 0; i < 2; i++) {
        int id = t + 256 * i;
        int row = id >> 3;
        int c = id & 7;
        uint32_t soff = (uint32_t)(row * ASHB + c * 16);
        cp16(sdst + AK_H + soff,
             kh + (size_t)(keyBase + row) * DIM + hcol + c * 8);
        cp16(sdst + AK_L + soff,
             kl + (size_t)(keyBase + row) * DIM + hcol + c * 8);
        cp16(sdst + AV_H + soff,
             vth + (size_t)(vtBase + row) * SLEN + vtCol + c * 8);
        cp16(sdst + AV_L + soff,
             vtl + (size_t)(vtBase + row) * SLEN + vtCol + c * 8);
    }
    if (t < ATK) {
        float add = mk[b * SLEN + kb * ATK + t] ? -1e30f : 0.0f;
        asm volatile("st.shared.f32 [%0], %1;" :: "r"(smsk + t * 4), "f"(add));
    }
    cp_commit();
}

__global__ __launch_bounds__(256, 2)
void attn_mma_kernel(const __nv_bfloat16* __restrict__ qh,
                     const __nv_bfloat16* __restrict__ ql,
                     const __nv_bfloat16* __restrict__ kh,
                     const __nv_bfloat16* __restrict__ kl,
                     const __nv_bfloat16* __restrict__ vth,
                     const __nv_bfloat16* __restrict__ vtl,
                     const unsigned char* __restrict__ mk,
                     __nv_bfloat16* __restrict__ Oh,
                     __nv_bfloat16* __restrict__ Ol) {
    extern __shared__ __align__(128) unsigned char smem[];
    const uint32_t sbase = smem_u32(smem);

    const int t = threadIdx.x;
    const int lane = t & 31;
    const int w = t >> 5;
    const int group = lane >> 2;
    const int tc4 = (lane & 3) * 4;

    const int qb = blockIdx.x;
    const int h  = blockIdx.y;
    const int b  = blockIdx.z;
    const int qBase = b * SLEN + qb * ATQ;
    const int hcol  = h * HD;

    const float qscale = 0.125f * 1.44269504088896340736f;

#pragma unroll
    for (int i = 0; i < 4; i++) {
        int id = t + 256 * i;
        int row = id >> 3;
        int c = id & 7;
        uint32_t soff = (uint32_t)(row * ASHB + c * 16);
        cp16(sbase + AQ_H + soff, qh + (size_t)(qBase + row) * DIM + hcol + c * 8);
        cp16(sbase + AQ_L + soff, ql + (size_t)(qBase + row) * DIM + hcol + c * 8);
    }
    cp_commit();
    attn_load_stage(sbase, kh, kl, vth, vtl, mk, b, hcol, 0, t);
    attn_load_stage(sbase, kh, kl, vth, vtl, mk, b, hcol, 1, t);

    float o[8][4];
    float m_i[2], l_i[2];
#pragma unroll
    for (int g = 0; g < 8; g++)
#pragma unroll
        for (int r = 0; r < 4; r++) o[g][r] = 0.0f;
    m_i[0] = m_i[1] = -1e30f;
    l_i[0] = l_i[1] = 0.0f;

    const int NT = SLEN / ATK;   // 16
    for (int kb = 0; kb < NT; kb++) {
        if (kb == NT - 1) cp_wait<0>(); else cp_wait<1>();
        __syncthreads();

        const unsigned char* stg = smem + AST0 + (kb & 1) * ASTAGE_BYTES;
        const unsigned char* pKh = stg + AK_H;
        const unsigned char* pKl = stg + AK_L;
        const unsigned char* pVh = stg + AV_H;
        const unsigned char* pVl = stg + AV_L;
        const float* madd =
            reinterpret_cast<const float*>(smem + AMSK + (kb & 1) * 256);

        float s[8][4];
#pragma unroll
        for (int g = 0; g < 8; g++)
#pragma unroll
            for (int r = 0; r < 4; r++) s[g][r] = 0.0f;

        const unsigned char* pQh = smem + AQ_H;
        const unsigned char* pQl = smem + AQ_L;
#pragma unroll
        for (int k = 0; k < 4; k++) {
            const int cb = tc4 + k * 32;
            uint32_t ah[4], al[4];
            int abase = (w * 16 + group) * ASHB + cb;
            ah[0] = *(const uint32_t*)(pQh + abase);
            ah[1] = *(const uint32_t*)(pQh + abase + 8 * ASHB);
            ah[2] = *(const uint32_t*)(pQh + abase + 16);
            ah[3] = *(const uint32_t*)(pQh + abase + 8 * ASHB + 16);
            al[0] = *(const uint32_t*)(pQl + abase);
            al[1] = *(const uint32_t*)(pQl + abase + 8 * ASHB);
            al[2] = *(const uint32_t*)(pQl + abase + 16);
            al[3] = *(const uint32_t*)(pQl + abase + 8 * ASHB + 16);
#pragma unroll
            for (int g = 0; g < 8; g++) {
                int bbase = (g * 8 + group) * ASHB + cb;
                uint32_t bh[2], bl[2];
                bh[0] = *(const uint32_t*)(pKh + bbase);
                bh[1] = *(const uint32_t*)(pKh + bbase + 16);
                bl[0] = *(const uint32_t*)(pKl + bbase);
                bl[1] = *(const uint32_t*)(pKl + bbase + 16);
                mma_bf16(s[g], ah, bh);
                mma_bf16(s[g], ah, bl);
                mma_bf16(s[g], al, bh);
            }
        }

#pragma unroll
        for (int g = 0; g < 8; g++) {
            float2 ma = *reinterpret_cast<const float2*>(
                &madd[g * 8 + (lane & 3) * 2]);
            s[g][0] = fmaf(s[g][0], qscale, ma.x);
            s[g][1] = fmaf(s[g][1], qscale, ma.y);
            s[g][2] = fmaf(s[g][2], qscale, ma.x);
            s[g][3] = fmaf(s[g][3], qscale, ma.y);
        }
        float mx0 = -1e30f, mx1 = -1e30f;
#pragma unroll
        for (int g = 0; g < 8; g++) {
            mx0 = fmaxf(mx0, fmaxf(s[g][0], s[g][1]));
            mx1 = fmaxf(mx1, fmaxf(s[g][2], s[g][3]));
        }
        mx0 = fmaxf(mx0, __shfl_xor_sync(0xffffffffu, mx0, 1));
        mx0 = fmaxf(mx0, __shfl_xor_sync(0xffffffffu, mx0, 2));
        mx1 = fmaxf(mx1, __shfl_xor_sync(0xffffffffu, mx1, 1));
        mx1 = fmaxf(mx1, __shfl_xor_sync(0xffffffffu, mx1, 2));
        float mn0 = fmaxf(m_i[0], mx0);
        float mn1 = fmaxf(m_i[1], mx1);
        float corr0 = exp2f(m_i[0] - mn0);
        float corr1 = exp2f(m_i[1] - mn1);
        m_i[0] = mn0; m_i[1] = mn1;

        uint32_t pah[4][4], pal[4][4];
        float sum0 = 0.0f, sum1 = 0.0f;
#pragma unroll
        for (int g = 0; g < 8; g++) {
            float p0 = exp2f(s[g][0] - mn0);
            float p1 = exp2f(s[g][1] - mn0);
            float p2 = exp2f(s[g][2] - mn1);
            float p3 = exp2f(s[g][3] - mn1);
            sum0 += p0 + p1;
            sum1 += p2 + p3;
            const int kc = g >> 1;
            const int o2 = (g & 1) * 2;
            pah[kc][o2 + 0] = pack_bf16x2(p0, p1);
            pah[kc][o2 + 1] = pack_bf16x2(p2, p3);
            pal[kc][o2 + 0] = pack_bf16x2(bf16_residual(p0), bf16_residual(p1));
            pal[kc][o2 + 1] = pack_bf16x2(bf16_residual(p2), bf16_residual(p3));
        }
        sum0 += __shfl_xor_sync(0xffffffffu, sum0, 1);
        sum0 += __shfl_xor_sync(0xffffffffu, sum0, 2);
        sum1 += __shfl_xor_sync(0xffffffffu, sum1, 1);
        sum1 += __shfl_xor_sync(0xffffffffu, sum1, 2);
        l_i[0] = l_i[0] * corr0 + sum0;
        l_i[1] = l_i[1] * corr1 + sum1;
#pragma unroll
        for (int g = 0; g < 8; g++) {
            o[g][0] *= corr0; o[g][1] *= corr0;
            o[g][2] *= corr1; o[g][3] *= corr1;
        }

#pragma unroll
        for (int kc = 0; kc < 4; kc++) {
            const int cb = tc4 + kc * 32;
#pragma unroll
            for (int d = 0; d < 8; d++) {
                int bbase = (d * 8 + group) * ASHB + cb;
                uint32_t bh[2], bl[2];
                bh[0] = *(const uint32_t*)(pVh + bbase);
                bh[1] = *(const uint32_t*)(pVh + bbase + 16);
                bl[0] = *(const uint32_t*)(pVl + bbase);
                bl[1] = *(const uint32_t*)(pVl + bbase + 16);
                mma_bf16(o[d], pah[kc], bh);
                mma_bf16(o[d], pah[kc], bl);
                mma_bf16(o[d], pal[kc], bh);
            }
        }
        __syncthreads();

        if (kb + 2 < NT)
            attn_load_stage(sbase, kh, kl, vth, vtl, mk, b, hcol, kb + 2, t);
    }

    float inv0 = 1.0f / l_i[0];
    float inv1 = 1.0f / l_i[1];
    const int gr0 = qBase + w * 16 + group;
#pragma unroll
    for (int g = 0; g < 8; g++) {
        int col = hcol + g * 8 + (lane & 3) * 2;
        float v0 = o[g][0] * inv0, v1 = o[g][1] * inv0;
        float v2 = o[g][2] * inv1, v3 = o[g][3] * inv1;
        *reinterpret_cast<uint32_t*>(&Oh[(size_t)gr0 * DIM + col]) =
            pack_bf16x2(v0, v1);
        *reinterpret_cast<uint32_t*>(&Ol[(size_t)gr0 * DIM + col]) =
            pack_bf16x2(bf16_residual(v0), bf16_residual(v1));
        *reinterpret_cast<uint32_t*>(&Oh[(size_t)(gr0 + 8) * DIM + col]) =
            pack_bf16x2(v2, v3);
        *reinterpret_cast<uint32_t*>(&Ol[(size_t)(gr0 + 8) * DIM + col]) =
            pack_bf16x2(bf16_residual(v2), bf16_residual(v3));
    }
}

// ---------------------------------------------------------------------------
// Launcher. Launch order puts the Q-projection GEMM at user-launch idx 3,
// which is the slot the ncu capture lands on (measured R10):
//   0: split  1: t0  2: t1  3: gemmQ <- capture  4: t2  5: t3
//   6: gemmK  7: gemmV  8: transpose_v  9: attn  10: gemmO
// ---------------------------------------------------------------------------
extern "C" void kernel_launch(void* const* d_in, const int* in_sizes, int n_in,
                              void* d_out, int out_size) {
    (void)in_sizes; (void)n_in; (void)out_size;
    const float* x          = (const float*)d_in[0];
    const unsigned char* mk = (const unsigned char*)d_in[1];
    const float* w[4] = {(const float*)d_in[2], (const float*)d_in[4],
                         (const float*)d_in[6], (const float*)d_in[8]};
    const float* bq = (const float*)d_in[3];
    const float* bk = (const float*)d_in[5];
    const float* bv = (const float*)d_in[7];
    const float* bo = (const float*)d_in[9];
    float* out = (float*)d_out;

    __nv_bfloat16 *xh, *xl, *qhp, *qlp, *khp, *klp, *vhp, *vlp;
    __nv_bfloat16 *vth, *vtl, *ah, *al, *wth, *wtl;
    cudaGetSymbolAddress((void**)&xh, g_x_hi);
    cudaGetSymbolAddress((void**)&xl, g_x_lo);
    cudaGetSymbolAddress((void**)&qhp, g_q_hi);
    cudaGetSymbolAddress((void**)&qlp, g_q_lo);
    cudaGetSymbolAddress((void**)&khp, g_k_hi);
    cudaGetSymbolAddress((void**)&klp, g_k_lo);
    cudaGetSymbolAddress((void**)&vhp, g_v_hi);
    cudaGetSymbolAddress((void**)&vlp, g_v_lo);
    cudaGetSymbolAddress((void**)&vth, g_vt_hi);
    cudaGetSymbolAddress((void**)&vtl, g_vt_lo);
    cudaGetSymbolAddress((void**)&ah, g_a_hi);
    cudaGetSymbolAddress((void**)&al, g_a_lo);
    cudaGetSymbolAddress((void**)&wth, g_wt_hi);
    cudaGetSymbolAddress((void**)&wtl, g_wt_lo);

    const int n4 = M_ROWS * DIM / 4;
    dim3 tgrid(DIM / 32, DIM / 32);

    cudaFuncSetAttribute(mma_gemm_kernel<0>,
                         cudaFuncAttributeMaxDynamicSharedMemorySize, GEMM_SMEM);
    cudaFuncSetAttribute(mma_gemm_kernel<1>,
                         cudaFuncAttributeMaxDynamicSharedMemorySize, GEMM_SMEM);
    cudaFuncSetAttribute(attn_mma_kernel,
                         cudaFuncAttributeMaxDynamicSharedMemorySize, ATTN_SMEM);
    dim3 ggrid(DIM / BN, M_ROWS / BM);

    // idx 0: x split
    split_kernel<<<(n4 + 255) / 256, 256>>>(x, xh, xl, n4);
    // idx 1,2: Q and K weight transposes
    transpose_split_kernel<<<tgrid, dim3(32, 8)>>>(
        w[0], wth + 0 * (size_t)DIM * DIM, wtl + 0 * (size_t)DIM * DIM);
    transpose_split_kernel<<<tgrid, dim3(32, 8)>>>(
        w[1], wth + 1 * (size_t)DIM * DIM, wtl + 1 * (size_t)DIM * DIM);
    // idx 3: Q GEMM  <-- ncu capture target
    mma_gemm_kernel<1><<<ggrid, 256, GEMM_SMEM>>>(
        xh, xl, wth + 0 * (size_t)DIM * DIM, wtl + 0 * (size_t)DIM * DIM, bq,
        nullptr, qhp, qlp);
    // idx 4,5: V and O weight transposes
    transpose_split_kernel<<<tgrid, dim3(32, 8)>>>(
        w[2], wth + 2 * (size_t)DIM * DIM, wtl + 2 * (size_t)DIM * DIM);
    transpose_split_kernel<<<tgrid, dim3(32, 8)>>>(
        w[3], wth + 3 * (size_t)DIM * DIM, wtl + 3 * (size_t)DIM * DIM);
    // idx 6,7: K and V GEMMs
    mma_gemm_kernel<1><<<ggrid, 256, GEMM_SMEM>>>(
        xh, xl, wth + 1 * (size_t)DIM * DIM, wtl + 1 * (size_t)DIM * DIM, bk,
        nullptr, khp, klp);
    mma_gemm_kernel<1><<<ggrid, 256, GEMM_SMEM>>>(
        xh, xl, wth + 2 * (size_t)DIM * DIM, wtl + 2 * (size_t)DIM * DIM, bv,
        nullptr, vhp, vlp);
    // idx 8: V transpose
    transpose_v_kernel<<<dim3(32, 32, 4), dim3(32, 8)>>>(vhp, vlp, vth, vtl);
    // idx 9: attention
    attn_mma_kernel<<<dim3(SLEN / ATQ, NH, 4), 256, ATTN_SMEM>>>(
        qhp, qlp, khp, klp, vth, vtl, mk, ah, al);
    // idx 10: output GEMM
    mma_gemm_kernel<0><<<ggrid, 256, GEMM_SMEM>>>(
        ah, al, wth + 3 * (size_t)DIM * DIM, wtl + 3 * (size_t)DIM * DIM, bo,
        out, nullptr, nullptr);
}

// round 12
// speedup vs baseline: 1.0970x; 1.0826x over previous
#include <cuda_runtime.h>
#include <cuda_bf16.h>
#include <math.h>
#include <stdint.h>

// Problem constants
#define M_ROWS 4096   // B*S
#define DIM    1024   // H
#define SLEN   1024
#define NH     16
#define HD     64

// ---------------------------------------------------------------------------
// Scratch (allocation-free rule: __device__ globals)
// ---------------------------------------------------------------------------
__device__ __nv_bfloat16 g_x_hi[M_ROWS * DIM];
__device__ __nv_bfloat16 g_x_lo[M_ROWS * DIM];
__device__ __nv_bfloat16 g_q_hi[M_ROWS * DIM];
__device__ __nv_bfloat16 g_q_lo[M_ROWS * DIM];
__device__ __nv_bfloat16 g_k_hi[M_ROWS * DIM];
__device__ __nv_bfloat16 g_k_lo[M_ROWS * DIM];
__device__ __nv_bfloat16 g_v_hi[M_ROWS * DIM];
__device__ __nv_bfloat16 g_v_lo[M_ROWS * DIM];
__device__ __nv_bfloat16 g_vt_hi[M_ROWS * DIM];   // per-batch transposed V
__device__ __nv_bfloat16 g_vt_lo[M_ROWS * DIM];
__device__ __nv_bfloat16 g_a_hi[M_ROWS * DIM];    // attention output (split)
__device__ __nv_bfloat16 g_a_lo[M_ROWS * DIM];
__device__ __nv_bfloat16 g_wt_hi[4][DIM * DIM];   // transposed+split weights [N][K]
__device__ __nv_bfloat16 g_wt_lo[4][DIM * DIM];

// ---------------------------------------------------------------------------
// helpers
// ---------------------------------------------------------------------------
__device__ __forceinline__ uint32_t smem_u32(const void* p) {
    uint32_t a;
    asm("{ .reg .u64 t; cvta.to.shared.u64 t, %1; cvt.u32.u64 %0, t; }"
        : "=r"(a) : "l"(p));
    return a;
}
__device__ __forceinline__ void cp16(uint32_t dst, const void* src) {
    asm volatile("cp.async.cg.shared.global [%0], [%1], 16;"
                 :: "r"(dst), "l"(src));
}
__device__ __forceinline__ void cp_commit() {
    asm volatile("cp.async.commit_group;");
}
template <int N>
__device__ __forceinline__ void cp_wait() {
    asm volatile("cp.async.wait_group %0;" :: "n"(N));
}

__device__ __forceinline__ void mma_bf16(float* c, const uint32_t* a,
                                         const uint32_t* b) {
    asm volatile(
        "mma.sync.aligned.m16n8k16.row.col.f32.bf16.bf16.f32 "
        "{%0,%1,%2,%3}, {%4,%5,%6,%7}, {%8,%9}, {%0,%1,%2,%3};\n"
        : "+f"(c[0]), "+f"(c[1]), "+f"(c[2]), "+f"(c[3])
        : "r"(a[0]), "r"(a[1]), "r"(a[2]), "r"(a[3]), "r"(b[0]), "r"(b[1]));
}

__device__ __forceinline__ void ldsm4(uint32_t* r, uint32_t addr) {
    asm volatile(
        "ldmatrix.sync.aligned.m8n8.x4.shared.b16 {%0,%1,%2,%3}, [%4];"
        : "=r"(r[0]), "=r"(r[1]), "=r"(r[2]), "=r"(r[3]) : "r"(addr));
}

__device__ __forceinline__ uint32_t pack_bf16x2(float x, float y) {
    __nv_bfloat162 h = __floats2bfloat162_rn(x, y);
    return *reinterpret_cast<uint32_t*>(&h);
}
__device__ __forceinline__ float bf16_residual(float x) {
    return x - __bfloat162float(__float2bfloat16(x));
}

// ---------------------------------------------------------------------------
// Split: x (fp32) -> (hi, lo) bf16
// ---------------------------------------------------------------------------
__global__ void split_kernel(const float* __restrict__ in,
                             __nv_bfloat16* __restrict__ hi,
                             __nv_bfloat16* __restrict__ lo, int n4) {
    int i = blockIdx.x * blockDim.x + threadIdx.x;
    if (i >= n4) return;
    float4 x = reinterpret_cast<const float4*>(in)[i];
    uint32_t* hp = reinterpret_cast<uint32_t*>(hi);
    uint32_t* lp = reinterpret_cast<uint32_t*>(lo);
    hp[2 * i]     = pack_bf16x2(x.x, x.y);
    hp[2 * i + 1] = pack_bf16x2(x.z, x.w);
    lp[2 * i]     = pack_bf16x2(bf16_residual(x.x), bf16_residual(x.y));
    lp[2 * i + 1] = pack_bf16x2(bf16_residual(x.z), bf16_residual(x.w));
}

// ---------------------------------------------------------------------------
// Transpose + split: W[K][N] fp32 -> Wt_hi[N][K], Wt_lo[N][K] bf16
// ---------------------------------------------------------------------------
__global__ void transpose_split_kernel(const float* __restrict__ W,
                                       __nv_bfloat16* __restrict__ t_hi,
                                       __nv_bfloat16* __restrict__ t_lo) {
    __shared__ float tile[32][33];
    const int tx = threadIdx.x;
    const int ty = threadIdx.y;
    const int k0 = blockIdx.y * 32;
    const int n0 = blockIdx.x * 32;
#pragma unroll
    for (int i = 0; i < 4; i++)
        tile[ty + 8 * i][tx] = W[(size_t)(k0 + ty + 8 * i) * DIM + n0 + tx];
    __syncthreads();
#pragma unroll
    for (int i = 0; i < 4; i++) {
        float v = tile[tx][ty + 8 * i];
        size_t o = (size_t)(n0 + ty + 8 * i) * DIM + k0 + tx;
        t_hi[o] = __float2bfloat16(v);
        t_lo[o] = __float2bfloat16(bf16_residual(v));
    }
}

// ---------------------------------------------------------------------------
// Per-batch bf16 transpose: vt[b*1024 + col][s] = v[b*1024 + s][col]
// ---------------------------------------------------------------------------
__global__ void transpose_v_kernel(const __nv_bfloat16* __restrict__ vh,
                                   const __nv_bfloat16* __restrict__ vl,
                                   __nv_bfloat16* __restrict__ th,
                                   __nv_bfloat16* __restrict__ tl) {
    __shared__ __nv_bfloat16 tileh[32][33];
    __shared__ __nv_bfloat16 tilel[32][33];
    const int tx = threadIdx.x;
    const int ty = threadIdx.y;
    const int c0 = blockIdx.x * 32;
    const int s0 = blockIdx.y * 32;
    const int b  = blockIdx.z;
    const size_t base = (size_t)b * SLEN * DIM;
#pragma unroll
    for (int i = 0; i < 4; i++) {
        int s = s0 + ty + 8 * i;
        tileh[ty + 8 * i][tx] = vh[base + (size_t)s * DIM + c0 + tx];
        tilel[ty + 8 * i][tx] = vl[base + (size_t)s * DIM + c0 + tx];
    }
    __syncthreads();
#pragma unroll
    for (int i = 0; i < 4; i++) {
        int c = c0 + ty + 8 * i;
        th[base + (size_t)c * SLEN + s0 + tx] = tileh[tx][ty + 8 * i];
        tl[base + (size_t)c * SLEN + s0 + tx] = tilel[tx][ty + 8 * i];
    }
}

// ---------------------------------------------------------------------------
// bf16x3 tensor-core GEMM: C[4096,1024] = A @ W + bias
// ldmatrix.x4 loads; 2-stage cp.async pipeline; 2 CTAs/SM (reg cap 128);
// MMA pass-reordered (hh, hl, lh outermost) for dependency distance 16.
// OSPLIT=0: fp32 C out; OSPLIT=1: split bf16 (Chi, Clo) out.
// ---------------------------------------------------------------------------
#define BM 128
#define BN 128
#define BK 32
#define SH 40
#define SHB (SH * 2)                      // 80-byte smem row stride
#define MAT_BYTES (128 * SHB)
#define STAGE_BYTES (4 * MAT_BYTES)       // 40960
#define NSTAGE 2
#define GEMM_SMEM (NSTAGE * STAGE_BYTES)  // 81920 -> 2 CTAs/SM
#define OFF_AHI 0
#define OFF_ALO MAT_BYTES
#define OFF_BHI (2 * MAT_BYTES)
#define OFF_BLO (3 * MAT_BYTES)

__device__ __forceinline__ void load_stage(uint32_t sdst,
                                           const __nv_bfloat16* __restrict__ A_hi,
                                           const __nv_bfloat16* __restrict__ A_lo,
                                           const __nv_bfloat16* __restrict__ B_hi,
                                           const __nv_bfloat16* __restrict__ B_lo,
                                           int rowBase, int colBase, int k0,
                                           int t) {
#pragma unroll
    for (int i = 0; i < 2; i++) {
        int id = t + 256 * i;
        int row = id >> 2;
        int c = id & 3;
        uint32_t soff = (uint32_t)(row * SHB + c * 16);
        const __nv_bfloat16* ah = A_hi + (size_t)(rowBase + row) * DIM + k0 + c * 8;
        const __nv_bfloat16* al = A_lo + (size_t)(rowBase + row) * DIM + k0 + c * 8;
        const __nv_bfloat16* bh = B_hi + (size_t)(colBase + row) * DIM + k0 + c * 8;
        const __nv_bfloat16* bl = B_lo + (size_t)(colBase + row) * DIM + k0 + c * 8;
        cp16(sdst + OFF_AHI + soff, ah);
        cp16(sdst + OFF_ALO + soff, al);
        cp16(sdst + OFF_BHI + soff, bh);
        cp16(sdst + OFF_BLO + soff, bl);
    }
    cp_commit();
}

template <int OSPLIT>
__global__ __launch_bounds__(256, 2)
void mma_gemm_kernel(const __nv_bfloat16* __restrict__ A_hi,
                     const __nv_bfloat16* __restrict__ A_lo,
                     const __nv_bfloat16* __restrict__ B_hi,
                     const __nv_bfloat16* __restrict__ B_lo,
                     const float* __restrict__ bias, float* __restrict__ C,
                     __nv_bfloat16* __restrict__ Chi,
                     __nv_bfloat16* __restrict__ Clo) {
    extern __shared__ __align__(128) unsigned char smem[];
    const uint32_t sbase = smem_u32(smem);

    const int t = threadIdx.x;
    const int lane = t & 31;
    const int wid = t >> 5;
    const int warp_m = wid & 3;
    const int warp_n = wid >> 2;
    const int group = lane >> 2;

    // per-lane ldmatrix offsets
    const int lr = lane & 7;
    const int lm = lane >> 3;                 // matrix index 0..3
    const int aRowOff = (warp_m * 32 + ((lm & 1) << 3) + lr) * SHB;
    const int aColOff = (lm >> 1) * 16;       // k+8 half
    const int bRowOff = (warp_n * 64 + ((lm >> 1) << 3) + lr) * SHB;
    const int bColOff = (lm & 1) * 16;

    const int rowBase = blockIdx.y * BM;
    const int colBase = blockIdx.x * BN;

    float acc[2][8][4];
#pragma unroll
    for (int f = 0; f < 2; f++)
#pragma unroll
        for (int g = 0; g < 8; g++)
#pragma unroll
            for (int r = 0; r < 4; r++) acc[f][g][r] = 0.0f;

#pragma unroll
    for (int s = 0; s < NSTAGE; s++)
        load_stage(sbase + s * STAGE_BYTES, A_hi, A_lo, B_hi, B_lo,
                   rowBase, colBase, s * BK, t);

    const int NCHUNK = DIM / BK;   // 32
    for (int c = 0; c < NCHUNK; c++) {
        if (c < NCHUNK - 1) cp_wait<1>();
        else cp_wait<0>();
        __syncthreads();

        const uint32_t stg = sbase + (uint32_t)((c % NSTAGE) * STAGE_BYTES);

#pragma unroll
        for (int ks = 0; ks < 2; ks++) {
            const int kcb = ks * 32;
            uint32_t ah[2][4], al[2][4], bh[8][2], bl[8][2];
#pragma unroll
            for (int f = 0; f < 2; f++) {
                uint32_t aoff = (uint32_t)(aRowOff + f * 16 * SHB + kcb + aColOff);
                ldsm4(ah[f], stg + OFF_AHI + aoff);
                ldsm4(al[f], stg + OFF_ALO + aoff);
            }
#pragma unroll
            for (int gp = 0; gp < 4; gp++) {
                uint32_t boff = (uint32_t)(bRowOff + gp * 16 * SHB + kcb + bColOff);
                ldsm4(&bh[2 * gp][0], stg + OFF_BHI + boff);
                ldsm4(&bl[2 * gp][0], stg + OFF_BLO + boff);
            }
            // pass-reordered: per-acc order stays hh -> hl -> lh (bit-identical),
            // but each acc is revisited only after 15 independent MMAs.
#pragma unroll
            for (int f = 0; f < 2; f++)
#pragma unroll
                for (int g = 0; g < 8; g++)
                    mma_bf16(acc[f][g], ah[f], bh[g]);
#pragma unroll
            for (int f = 0; f < 2; f++)
#pragma unroll
                for (int g = 0; g < 8; g++)
                    mma_bf16(acc[f][g], ah[f], bl[g]);
#pragma unroll
            for (int f = 0; f < 2; f++)
#pragma unroll
                for (int g = 0; g < 8; g++)
                    mma_bf16(acc[f][g], al[f], bh[g]);
        }
        __syncthreads();

        if (c + NSTAGE < NCHUNK)
            load_stage(sbase + (c % NSTAGE) * STAGE_BYTES, A_hi, A_lo, B_hi,
                       B_lo, rowBase, colBase, (c + NSTAGE) * BK, t);
    }

#pragma unroll
    for (int g = 0; g < 8; g++) {
        int col0 = colBase + warp_n * 64 + g * 8 + (lane & 3) * 2;
        float2 bb = *reinterpret_cast<const float2*>(&bias[col0]);
#pragma unroll
        for (int f = 0; f < 2; f++) {
            int r0 = rowBase + warp_m * 32 + f * 16 + group;
            float v0 = acc[f][g][0] + bb.x, v1 = acc[f][g][1] + bb.y;
            float v2 = acc[f][g][2] + bb.x, v3 = acc[f][g][3] + bb.y;
            if (OSPLIT) {
                *reinterpret_cast<uint32_t*>(&Chi[(size_t)r0 * DIM + col0]) =
                    pack_bf16x2(v0, v1);
                *reinterpret_cast<uint32_t*>(&Clo[(size_t)r0 * DIM + col0]) =
                    pack_bf16x2(bf16_residual(v0), bf16_residual(v1));
                *reinterpret_cast<uint32_t*>(&Chi[(size_t)(r0 + 8) * DIM + col0]) =
                    pack_bf16x2(v2, v3);
                *reinterpret_cast<uint32_t*>(&Clo[(size_t)(r0 + 8) * DIM + col0]) =
                    pack_bf16x2(bf16_residual(v2), bf16_residual(v3));
            } else {
                *reinterpret_cast<float2*>(&C[(size_t)r0 * DIM + col0]) =
                    make_float2(v0, v1);
                *reinterpret_cast<float2*>(&C[(size_t)(r0 + 8) * DIM + col0]) =
                    make_float2(v2, v3);
            }
        }
    }
}

// ---------------------------------------------------------------------------
// Tensor-core flash attention, register-resident P (unchanged from R8 WIN)
// ---------------------------------------------------------------------------
#define ATQ 128
#define ATK 64
#define ASHB 144                        // smem row stride bytes (72 bf16)
#define AQ_H 0
#define AQ_L (ATQ * ASHB)               // 18432
#define AST0 (2 * ATQ * ASHB)           // 36864
#define ASTAGE_BYTES (4 * ATK * ASHB)   // 36864 (kh,kl,vth,vtl)
#define AK_H 0
#define AK_L (ATK * ASHB)
#define AV_H (2 * ATK * ASHB)
#define AV_L (3 * ATK * ASHB)
#define AMSK (AST0 + 2 * ASTAGE_BYTES)  // 110592, 2 x 64 floats
#define ATTN_SMEM (AMSK + 2 * 256)      // 111104

__device__ __forceinline__ void attn_load_stage(
    uint32_t sbase,
    const __nv_bfloat16* kh, const __nv_bfloat16* kl,
    const __nv_bfloat16* vth, const __nv_bfloat16* vtl,
    const unsigned char* mk,
    int b, int hcol, int kb, int t) {
    const uint32_t sdst = sbase + AST0 + (uint32_t)(kb & 1) * ASTAGE_BYTES;
    const uint32_t smsk = sbase + AMSK + (uint32_t)(kb & 1) * 256;
    const int keyBase = b * SLEN + kb * ATK;
    const int vtBase  = b * SLEN + hcol;
    const int vtCol   = kb * ATK;
#pragma unroll
    for (int i = 0; i < 2; i++) {
        int id = t + 256 * i;
        int row = id >> 3;
        int c = id & 7;
        uint32_t soff = (uint32_t)(row * ASHB + c * 16);
        cp16(sdst + AK_H + soff,
             kh + (size_t)(keyBase + row) * DIM + hcol + c * 8);
        cp16(sdst + AK_L + soff,
             kl + (size_t)(keyBase + row) * DIM + hcol + c * 8);
        cp16(sdst + AV_H + soff,
             vth + (size_t)(vtBase + row) * SLEN + vtCol + c * 8);
        cp16(sdst + AV_L + soff,
             vtl + (size_t)(vtBase + row) * SLEN + vtCol + c * 8);
    }
    if (t < ATK) {
        float add = mk[b * SLEN + kb * ATK + t] ? -1e30f : 0.0f;
        asm volatile("st.shared.f32 [%0], %1;" :: "r"(smsk + t * 4), "f"(add));
    }
    cp_commit();
}

__global__ __launch_bounds__(256, 2)
void attn_mma_kernel(const __nv_bfloat16* __restrict__ qh,
                     const __nv_bfloat16* __restrict__ ql,
                     const __nv_bfloat16* __restrict__ kh,
                     const __nv_bfloat16* __restrict__ kl,
                     const __nv_bfloat16* __restrict__ vth,
                     const __nv_bfloat16* __restrict__ vtl,
                     const unsigned char* __restrict__ mk,
                     __nv_bfloat16* __restrict__ Oh,
                     __nv_bfloat16* __restrict__ Ol) {
    extern __shared__ __align__(128) unsigned char smem[];
    const uint32_t sbase = smem_u32(smem);

    const int t = threadIdx.x;
    const int lane = t & 31;
    const int w = t >> 5;
    const int group = lane >> 2;
    const int tc4 = (lane & 3) * 4;

    const int qb = blockIdx.x;
    const int h  = blockIdx.y;
    const int b  = blockIdx.z;
    const int qBase = b * SLEN + qb * ATQ;
    const int hcol  = h * HD;

    const float qscale = 0.125f * 1.44269504088896340736f;

#pragma unroll
    for (int i = 0; i < 4; i++) {
        int id = t + 256 * i;
        int row = id >> 3;
        int c = id & 7;
        uint32_t soff = (uint32_t)(row * ASHB + c * 16);
        cp16(sbase + AQ_H + soff, qh + (size_t)(qBase + row) * DIM + hcol + c * 8);
        cp16(sbase + AQ_L + soff, ql + (size_t)(qBase + row) * DIM + hcol + c * 8);
    }
    cp_commit();
    attn_load_stage(sbase, kh, kl, vth, vtl, mk, b, hcol, 0, t);
    attn_load_stage(sbase, kh, kl, vth, vtl, mk, b, hcol, 1, t);

    float o[8][4];
    float m_i[2], l_i[2];
#pragma unroll
    for (int g = 0; g < 8; g++)
#pragma unroll
        for (int r = 0; r < 4; r++) o[g][r] = 0.0f;
    m_i[0] = m_i[1] = -1e30f;
    l_i[0] = l_i[1] = 0.0f;

    const int NT = SLEN / ATK;   // 16
    for (int kb = 0; kb < NT; kb++) {
        if (kb == NT - 1) cp_wait<0>(); else cp_wait<1>();
        __syncthreads();

        const unsigned char* stg = smem + AST0 + (kb & 1) * ASTAGE_BYTES;
        const unsigned char* pKh = stg + AK_H;
        const unsigned char* pKl = stg + AK_L;
        const unsigned char* pVh = stg + AV_H;
        const unsigned char* pVl = stg + AV_L;
        const float* madd =
            reinterpret_cast<const float*>(smem + AMSK + (kb & 1) * 256);

        float s[8][4];
#pragma unroll
        for (int g = 0; g < 8; g++)
#pragma unroll
            for (int r = 0; r < 4; r++) s[g][r] = 0.0f;

        const unsigned char* pQh = smem + AQ_H;
        const unsigned char* pQl = smem + AQ_L;
#pragma unroll
        for (int k = 0; k < 4; k++) {
            const int cb = tc4 + k * 32;
            uint32_t ah[4], al[4];
            int abase = (w * 16 + group) * ASHB + cb;
            ah[0] = *(const uint32_t*)(pQh + abase);
            ah[1] = *(const uint32_t*)(pQh + abase + 8 * ASHB);
            ah[2] = *(const uint32_t*)(pQh + abase + 16);
            ah[3] = *(const uint32_t*)(pQh + abase + 8 * ASHB + 16);
            al[0] = *(const uint32_t*)(pQl + abase);
            al[1] = *(const uint32_t*)(pQl + abase + 8 * ASHB);
            al[2] = *(const uint32_t*)(pQl + abase + 16);
            al[3] = *(const uint32_t*)(pQl + abase + 8 * ASHB + 16);
#pragma unroll
            for (int g = 0; g < 8; g++) {
                int bbase = (g * 8 + group) * ASHB + cb;
                uint32_t bh[2], bl[2];
                bh[0] = *(const uint32_t*)(pKh + bbase);
                bh[1] = *(const uint32_t*)(pKh + bbase + 16);
                bl[0] = *(const uint32_t*)(pKl + bbase);
                bl[1] = *(const uint32_t*)(pKl + bbase + 16);
                mma_bf16(s[g], ah, bh);
                mma_bf16(s[g], ah, bl);
                mma_bf16(s[g], al, bh);
            }
        }

#pragma unroll
        for (int g = 0; g < 8; g++) {
            float2 ma = *reinterpret_cast<const float2*>(
                &madd[g * 8 + (lane & 3) * 2]);
            s[g][0] = fmaf(s[g][0], qscale, ma.x);
            s[g][1] = fmaf(s[g][1], qscale, ma.y);
            s[g][2] = fmaf(s[g][2], qscale, ma.x);
            s[g][3] = fmaf(s[g][3], qscale, ma.y);
        }
        float mx0 = -1e30f, mx1 = -1e30f;
#pragma unroll
        for (int g = 0; g < 8; g++) {
            mx0 = fmaxf(mx0, fmaxf(s[g][0], s[g][1]));
            mx1 = fmaxf(mx1, fmaxf(s[g][2], s[g][3]));
        }
        mx0 = fmaxf(mx0, __shfl_xor_sync(0xffffffffu, mx0, 1));
        mx0 = fmaxf(mx0, __shfl_xor_sync(0xffffffffu, mx0, 2));
        mx1 = fmaxf(mx1, __shfl_xor_sync(0xffffffffu, mx1, 1));
        mx1 = fmaxf(mx1, __shfl_xor_sync(0xffffffffu, mx1, 2));
        float mn0 = fmaxf(m_i[0], mx0);
        float mn1 = fmaxf(m_i[1], mx1);
        float corr0 = exp2f(m_i[0] - mn0);
        float corr1 = exp2f(m_i[1] - mn1);
        m_i[0] = mn0; m_i[1] = mn1;

        uint32_t pah[4][4], pal[4][4];
        float sum0 = 0.0f, sum1 = 0.0f;
#pragma unroll
        for (int g = 0; g < 8; g++) {
            float p0 = exp2f(s[g][0] - mn0);
            float p1 = exp2f(s[g][1] - mn0);
            float p2 = exp2f(s[g][2] - mn1);
            float p3 = exp2f(s[g][3] - mn1);
            sum0 += p0 + p1;
            sum1 += p2 + p3;
            const int kc = g >> 1;
            const int o2 = (g & 1) * 2;
            pah[kc][o2 + 0] = pack_bf16x2(p0, p1);
            pah[kc][o2 + 1] = pack_bf16x2(p2, p3);
            pal[kc][o2 + 0] = pack_bf16x2(bf16_residual(p0), bf16_residual(p1));
            pal[kc][o2 + 1] = pack_bf16x2(bf16_residual(p2), bf16_residual(p3));
        }
        sum0 += __shfl_xor_sync(0xffffffffu, sum0, 1);
        sum0 += __shfl_xor_sync(0xffffffffu, sum0, 2);
        sum1 += __shfl_xor_sync(0xffffffffu, sum1, 1);
        sum1 += __shfl_xor_sync(0xffffffffu, sum1, 2);
        l_i[0] = l_i[0] * corr0 + sum0;
        l_i[1] = l_i[1] * corr1 + sum1;
#pragma unroll
        for (int g = 0; g < 8; g++) {
            o[g][0] *= corr0; o[g][1] *= corr0;
            o[g][2] *= corr1; o[g][3] *= corr1;
        }

#pragma unroll
        for (int kc = 0; kc < 4; kc++) {
            const int cb = tc4 + kc * 32;
#pragma unroll
            for (int d = 0; d < 8; d++) {
                int bbase = (d * 8 + group) * ASHB + cb;
                uint32_t bh[2], bl[2];
                bh[0] = *(const uint32_t*)(pVh + bbase);
                bh[1] = *(const uint32_t*)(pVh + bbase + 16);
                bl[0] = *(const uint32_t*)(pVl + bbase);
                bl[1] = *(const uint32_t*)(pVl + bbase + 16);
                mma_bf16(o[d], pah[kc], bh);
                mma_bf16(o[d], pah[kc], bl);
                mma_bf16(o[d], pal[kc], bh);
            }
        }
        __syncthreads();

        if (kb + 2 < NT)
            attn_load_stage(sbase, kh, kl, vth, vtl, mk, b, hcol, kb + 2, t);
    }

    float inv0 = 1.0f / l_i[0];
    float inv1 = 1.0f / l_i[1];
    const int gr0 = qBase + w * 16 + group;
#pragma unroll
    for (int g = 0; g < 8; g++) {
        int col = hcol + g * 8 + (lane & 3) * 2;
        float v0 = o[g][0] * inv0, v1 = o[g][1] * inv0;
        float v2 = o[g][2] * inv1, v3 = o[g][3] * inv1;
        *reinterpret_cast<uint32_t*>(&Oh[(size_t)gr0 * DIM + col]) =
            pack_bf16x2(v0, v1);
        *reinterpret_cast<uint32_t*>(&Ol[(size_t)gr0 * DIM + col]) =
            pack_bf16x2(bf16_residual(v0), bf16_residual(v1));
        *reinterpret_cast<uint32_t*>(&Oh[(size_t)(gr0 + 8) * DIM + col]) =
            pack_bf16x2(v2, v3);
        *reinterpret_cast<uint32_t*>(&Ol[(size_t)(gr0 + 8) * DIM + col]) =
            pack_bf16x2(bf16_residual(v2), bf16_residual(v3));
    }
}

// ---------------------------------------------------------------------------
// Launcher. Q-projection GEMM at user-launch idx 3 = ncu capture slot:
//   0: split  1: t0  2: t1  3: gemmQ <- capture  4: t2  5: t3
//   6: gemmK  7: gemmV  8: transpose_v  9: attn  10: gemmO
// ---------------------------------------------------------------------------
extern "C" void kernel_launch(void* const* d_in, const int* in_sizes, int n_in,
                              void* d_out, int out_size) {
    (void)in_sizes; (void)n_in; (void)out_size;
    const float* x          = (const float*)d_in[0];
    const unsigned char* mk = (const unsigned char*)d_in[1];
    const float* w[4] = {(const float*)d_in[2], (const float*)d_in[4],
                         (const float*)d_in[6], (const float*)d_in[8]};
    const float* bq = (const float*)d_in[3];
    const float* bk = (const float*)d_in[5];
    const float* bv = (const float*)d_in[7];
    const float* bo = (const float*)d_in[9];
    float* out = (float*)d_out;

    __nv_bfloat16 *xh, *xl, *qhp, *qlp, *khp, *klp, *vhp, *vlp;
    __nv_bfloat16 *vth, *vtl, *ah, *al, *wth, *wtl;
    cudaGetSymbolAddress((void**)&xh, g_x_hi);
    cudaGetSymbolAddress((void**)&xl, g_x_lo);
    cudaGetSymbolAddress((void**)&qhp, g_q_hi);
    cudaGetSymbolAddress((void**)&qlp, g_q_lo);
    cudaGetSymbolAddress((void**)&khp, g_k_hi);
    cudaGetSymbolAddress((void**)&klp, g_k_lo);
    cudaGetSymbolAddress((void**)&vhp, g_v_hi);
    cudaGetSymbolAddress((void**)&vlp, g_v_lo);
    cudaGetSymbolAddress((void**)&vth, g_vt_hi);
    cudaGetSymbolAddress((void**)&vtl, g_vt_lo);
    cudaGetSymbolAddress((void**)&ah, g_a_hi);
    cudaGetSymbolAddress((void**)&al, g_a_lo);
    cudaGetSymbolAddress((void**)&wth, g_wt_hi);
    cudaGetSymbolAddress((void**)&wtl, g_wt_lo);

    const int n4 = M_ROWS * DIM / 4;
    dim3 tgrid(DIM / 32, DIM / 32);

    cudaFuncSetAttribute(mma_gemm_kernel<0>,
                         cudaFuncAttributeMaxDynamicSharedMemorySize, GEMM_SMEM);
    cudaFuncSetAttribute(mma_gemm_kernel<1>,
                         cudaFuncAttributeMaxDynamicSharedMemorySize, GEMM_SMEM);
    cudaFuncSetAttribute(attn_mma_kernel,
                         cudaFuncAttributeMaxDynamicSharedMemorySize, ATTN_SMEM);
    dim3 ggrid(DIM / BN, M_ROWS / BM);

    // idx 0: x split
    split_kernel<<<(n4 + 255) / 256, 256>>>(x, xh, xl, n4);
    // idx 1,2: Q and K weight transposes
    transpose_split_kernel<<<tgrid, dim3(32, 8)>>>(
        w[0], wth + 0 * (size_t)DIM * DIM, wtl + 0 * (size_t)DIM * DIM);
    transpose_split_kernel<<<tgrid, dim3(32, 8)>>>(
        w[1], wth + 1 * (size_t)DIM * DIM, wtl + 1 * (size_t)DIM * DIM);
    // idx 3: Q GEMM  <-- ncu capture target
    mma_gemm_kernel<1><<<ggrid, 256, GEMM_SMEM>>>(
        xh, xl, wth + 0 * (size_t)DIM * DIM, wtl + 0 * (size_t)DIM * DIM, bq,
        nullptr, qhp, qlp);
    // idx 4,5: V and O weight transposes
    transpose_split_kernel<<<tgrid, dim3(32, 8)>>>(
        w[2], wth + 2 * (size_t)DIM * DIM, wtl + 2 * (size_t)DIM * DIM);
    transpose_split_kernel<<<tgrid, dim3(32, 8)>>>(
        w[3], wth + 3 * (size_t)DIM * DIM, wtl + 3 * (size_t)DIM * DIM);
    // idx 6,7: K and V GEMMs
    mma_gemm_kernel<1><<<ggrid, 256, GEMM_SMEM>>>(
        xh, xl, wth + 1 * (size_t)DIM * DIM, wtl + 1 * (size_t)DIM * DIM, bk,
        nullptr, khp, klp);
    mma_gemm_kernel<1><<<ggrid, 256, GEMM_SMEM>>>(
        xh, xl, wth + 2 * (size_t)DIM * DIM, wtl + 2 * (size_t)DIM * DIM, bv,
        nullptr, vhp, vlp);
    // idx 8: V transpose
    transpose_v_kernel<<<dim3(32, 32, 4), dim3(32, 8)>>>(vhp, vlp, vth, vtl);
    // idx 9: attention
    attn_mma_kernel<<<dim3(SLEN / ATQ, NH, 4), 256, ATTN_SMEM>>>(
        qhp, qlp, khp, klp, vth, vtl, mk, ah, al);
    // idx 10: output GEMM
    mma_gemm_kernel<0><<<ggrid, 256, GEMM_SMEM>>>(
        ah, al, wth + 3 * (size_t)DIM * DIM, wtl + 3 * (size_t)DIM * DIM, bo,
        out, nullptr, nullptr);
}

// round 13
// speedup vs baseline: 1.1251x; 1.0257x over previous
#include <cuda_runtime.h>
#include <cuda_bf16.h>
#include <math.h>
#include <stdint.h>

// Problem constants
#define M_ROWS 4096   // B*S
#define DIM    1024   // H
#define SLEN   1024
#define NH     16
#define HD     64

// ---------------------------------------------------------------------------
// Scratch (allocation-free rule: __device__ globals)
// ---------------------------------------------------------------------------
__device__ __nv_bfloat16 g_x_hi[M_ROWS * DIM];
__device__ __nv_bfloat16 g_x_lo[M_ROWS * DIM];
__device__ __nv_bfloat16 g_q_hi[M_ROWS * DIM];
__device__ __nv_bfloat16 g_q_lo[M_ROWS * DIM];
__device__ __nv_bfloat16 g_k_hi[M_ROWS * DIM];
__device__ __nv_bfloat16 g_k_lo[M_ROWS * DIM];
__device__ __nv_bfloat16 g_v_hi[M_ROWS * DIM];
__device__ __nv_bfloat16 g_v_lo[M_ROWS * DIM];
__device__ __nv_bfloat16 g_vt_hi[M_ROWS * DIM];   // per-batch transposed V
__device__ __nv_bfloat16 g_vt_lo[M_ROWS * DIM];
__device__ __nv_bfloat16 g_a_hi[M_ROWS * DIM];    // attention output (split)
__device__ __nv_bfloat16 g_a_lo[M_ROWS * DIM];
__device__ __nv_bfloat16 g_wt_hi[4][DIM * DIM];   // transposed+split weights [N][K]
__device__ __nv_bfloat16 g_wt_lo[4][DIM * DIM];

// ---------------------------------------------------------------------------
// helpers
// ---------------------------------------------------------------------------
__device__ __forceinline__ uint32_t smem_u32(const void* p) {
    uint32_t a;
    asm("{ .reg .u64 t; cvta.to.shared.u64 t, %1; cvt.u32.u64 %0, t; }"
        : "=r"(a) : "l"(p));
    return a;
}
__device__ __forceinline__ void cp16(uint32_t dst, const void* src) {
    asm volatile("cp.async.cg.shared.global [%0], [%1], 16;"
                 :: "r"(dst), "l"(src));
}
__device__ __forceinline__ void cp_commit() {
    asm volatile("cp.async.commit_group;");
}
template <int N>
__device__ __forceinline__ void cp_wait() {
    asm volatile("cp.async.wait_group %0;" :: "n"(N));
}

__device__ __forceinline__ void mma_bf16(float* c, const uint32_t* a,
                                         const uint32_t* b) {
    asm volatile(
        "mma.sync.aligned.m16n8k16.row.col.f32.bf16.bf16.f32 "
        "{%0,%1,%2,%3}, {%4,%5,%6,%7}, {%8,%9}, {%0,%1,%2,%3};\n"
        : "+f"(c[0]), "+f"(c[1]), "+f"(c[2]), "+f"(c[3])
        : "r"(a[0]), "r"(a[1]), "r"(a[2]), "r"(a[3]), "r"(b[0]), "r"(b[1]));
}

__device__ __forceinline__ void ldsm4(uint32_t* r, uint32_t addr) {
    asm volatile(
        "ldmatrix.sync.aligned.m8n8.x4.shared.b16 {%0,%1,%2,%3}, [%4];"
        : "=r"(r[0]), "=r"(r[1]), "=r"(r[2]), "=r"(r[3]) : "r"(addr));
}

__device__ __forceinline__ uint32_t pack_bf16x2(float x, float y) {
    __nv_bfloat162 h = __floats2bfloat162_rn(x, y);
    return *reinterpret_cast<uint32_t*>(&h);
}
__device__ __forceinline__ float bf16_residual(float x) {
    return x - __bfloat162float(__float2bfloat16(x));
}

// ---------------------------------------------------------------------------
// Split: x (fp32) -> (hi, lo) bf16
// ---------------------------------------------------------------------------
__global__ void split_kernel(const float* __restrict__ in,
                             __nv_bfloat16* __restrict__ hi,
                             __nv_bfloat16* __restrict__ lo, int n4) {
    int i = blockIdx.x * blockDim.x + threadIdx.x;
    if (i >= n4) return;
    float4 x = reinterpret_cast<const float4*>(in)[i];
    uint32_t* hp = reinterpret_cast<uint32_t*>(hi);
    uint32_t* lp = reinterpret_cast<uint32_t*>(lo);
    hp[2 * i]     = pack_bf16x2(x.x, x.y);
    hp[2 * i + 1] = pack_bf16x2(x.z, x.w);
    lp[2 * i]     = pack_bf16x2(bf16_residual(x.x), bf16_residual(x.y));
    lp[2 * i + 1] = pack_bf16x2(bf16_residual(x.z), bf16_residual(x.w));
}

// ---------------------------------------------------------------------------
// Transpose + split: W[K][N] fp32 -> Wt_hi[N][K], Wt_lo[N][K] bf16
// ---------------------------------------------------------------------------
__global__ void transpose_split_kernel(const float* __restrict__ W,
                                       __nv_bfloat16* __restrict__ t_hi,
                                       __nv_bfloat16* __restrict__ t_lo) {
    __shared__ float tile[32][33];
    const int tx = threadIdx.x;
    const int ty = threadIdx.y;
    const int k0 = blockIdx.y * 32;
    const int n0 = blockIdx.x * 32;
#pragma unroll
    for (int i = 0; i < 4; i++)
        tile[ty + 8 * i][tx] = W[(size_t)(k0 + ty + 8 * i) * DIM + n0 + tx];
    __syncthreads();
#pragma unroll
    for (int i = 0; i < 4; i++) {
        float v = tile[tx][ty + 8 * i];
        size_t o = (size_t)(n0 + ty + 8 * i) * DIM + k0 + tx;
        t_hi[o] = __float2bfloat16(v);
        t_lo[o] = __float2bfloat16(bf16_residual(v));
    }
}

// ---------------------------------------------------------------------------
// Per-batch bf16 transpose: vt[b*1024 + col][s] = v[b*1024 + s][col]
// ---------------------------------------------------------------------------
__global__ void transpose_v_kernel(const __nv_bfloat16* __restrict__ vh,
                                   const __nv_bfloat16* __restrict__ vl,
                                   __nv_bfloat16* __restrict__ th,
                                   __nv_bfloat16* __restrict__ tl) {
    __shared__ __nv_bfloat16 tileh[32][33];
    __shared__ __nv_bfloat16 tilel[32][33];
    const int tx = threadIdx.x;
    const int ty = threadIdx.y;
    const int c0 = blockIdx.x * 32;
    const int s0 = blockIdx.y * 32;
    const int b  = blockIdx.z;
    const size_t base = (size_t)b * SLEN * DIM;
#pragma unroll
    for (int i = 0; i < 4; i++) {
        int s = s0 + ty + 8 * i;
        tileh[ty + 8 * i][tx] = vh[base + (size_t)s * DIM + c0 + tx];
        tilel[ty + 8 * i][tx] = vl[base + (size_t)s * DIM + c0 + tx];
    }
    __syncthreads();
#pragma unroll
    for (int i = 0; i < 4; i++) {
        int c = c0 + ty + 8 * i;
        th[base + (size_t)c * SLEN + s0 + tx] = tileh[tx][ty + 8 * i];
        tl[base + (size_t)c * SLEN + s0 + tx] = tilel[tx][ty + 8 * i];
    }
}

// ---------------------------------------------------------------------------
// bf16x3 tensor-core GEMM: C[4096,1024] = A @ W + bias
// ldmatrix.x4 loads; 2-stage cp.async pipeline with SINGLE sync per chunk;
// 2 CTAs/SM (reg cap 128); MMA pass-reordered (dep distance 16).
// OSPLIT=0: fp32 C out; OSPLIT=1: split bf16 (Chi, Clo) out.
// ---------------------------------------------------------------------------
#define BM 128
#define BN 128
#define BK 32
#define SH 40
#define SHB (SH * 2)                      // 80-byte smem row stride
#define MAT_BYTES (128 * SHB)
#define STAGE_BYTES (4 * MAT_BYTES)       // 40960
#define NSTAGE 2
#define GEMM_SMEM (NSTAGE * STAGE_BYTES)  // 81920 -> 2 CTAs/SM
#define OFF_AHI 0
#define OFF_ALO MAT_BYTES
#define OFF_BHI (2 * MAT_BYTES)
#define OFF_BLO (3 * MAT_BYTES)

__device__ __forceinline__ void load_stage(uint32_t sdst,
                                           const __nv_bfloat16* __restrict__ A_hi,
                                           const __nv_bfloat16* __restrict__ A_lo,
                                           const __nv_bfloat16* __restrict__ B_hi,
                                           const __nv_bfloat16* __restrict__ B_lo,
                                           int rowBase, int colBase, int k0,
                                           int t) {
#pragma unroll
    for (int i = 0; i < 2; i++) {
        int id = t + 256 * i;
        int row = id >> 2;
        int c = id & 3;
        uint32_t soff = (uint32_t)(row * SHB + c * 16);
        const __nv_bfloat16* ah = A_hi + (size_t)(rowBase + row) * DIM + k0 + c * 8;
        const __nv_bfloat16* al = A_lo + (size_t)(rowBase + row) * DIM + k0 + c * 8;
        const __nv_bfloat16* bh = B_hi + (size_t)(colBase + row) * DIM + k0 + c * 8;
        const __nv_bfloat16* bl = B_lo + (size_t)(colBase + row) * DIM + k0 + c * 8;
        cp16(sdst + OFF_AHI + soff, ah);
        cp16(sdst + OFF_ALO + soff, al);
        cp16(sdst + OFF_BHI + soff, bh);
        cp16(sdst + OFF_BLO + soff, bl);
    }
    cp_commit();
}

template <int OSPLIT>
__global__ __launch_bounds__(256, 2)
void mma_gemm_kernel(const __nv_bfloat16* __restrict__ A_hi,
                     const __nv_bfloat16* __restrict__ A_lo,
                     const __nv_bfloat16* __restrict__ B_hi,
                     const __nv_bfloat16* __restrict__ B_lo,
                     const float* __restrict__ bias, float* __restrict__ C,
                     __nv_bfloat16* __restrict__ Chi,
                     __nv_bfloat16* __restrict__ Clo) {
    extern __shared__ __align__(128) unsigned char smem[];
    const uint32_t sbase = smem_u32(smem);

    const int t = threadIdx.x;
    const int lane = t & 31;
    const int wid = t >> 5;
    const int warp_m = wid & 3;
    const int warp_n = wid >> 2;
    const int group = lane >> 2;

    // per-lane ldmatrix offsets
    const int lr = lane & 7;
    const int lm = lane >> 3;                 // matrix index 0..3
    const int aRowOff = (warp_m * 32 + ((lm & 1) << 3) + lr) * SHB;
    const int aColOff = (lm >> 1) * 16;       // k+8 half
    const int bRowOff = (warp_n * 64 + ((lm >> 1) << 3) + lr) * SHB;
    const int bColOff = (lm & 1) * 16;

    const int rowBase = blockIdx.y * BM;
    const int colBase = blockIdx.x * BN;

    float acc[2][8][4];
#pragma unroll
    for (int f = 0; f < 2; f++)
#pragma unroll
        for (int g = 0; g < 8; g++)
#pragma unroll
            for (int r = 0; r < 4; r++) acc[f][g][r] = 0.0f;

    // prologue: chunk 0 -> stage 0
    load_stage(sbase, A_hi, A_lo, B_hi, B_lo, rowBase, colBase, 0, t);

    const int NCHUNK = DIM / BK;   // 32
    for (int c = 0; c < NCHUNK; c++) {
        cp_wait<0>();              // chunk c resident
        __syncthreads();           // + all warps done computing chunk c-1

        // issue next load into the stage computed at c-1 (safe past sync)
        if (c + 1 < NCHUNK)
            load_stage(sbase + (uint32_t)(((c + 1) & 1) * STAGE_BYTES),
                       A_hi, A_lo, B_hi, B_lo, rowBase, colBase,
                       (c + 1) * BK, t);

        const uint32_t stg = sbase + (uint32_t)((c & 1) * STAGE_BYTES);

#pragma unroll
        for (int ks = 0; ks < 2; ks++) {
            const int kcb = ks * 32;
            uint32_t ah[2][4], al[2][4], bh[8][2], bl[8][2];
#pragma unroll
            for (int f = 0; f < 2; f++) {
                uint32_t aoff = (uint32_t)(aRowOff + f * 16 * SHB + kcb + aColOff);
                ldsm4(ah[f], stg + OFF_AHI + aoff);
                ldsm4(al[f], stg + OFF_ALO + aoff);
            }
#pragma unroll
            for (int gp = 0; gp < 4; gp++) {
                uint32_t boff = (uint32_t)(bRowOff + gp * 16 * SHB + kcb + bColOff);
                ldsm4(&bh[2 * gp][0], stg + OFF_BHI + boff);
                ldsm4(&bl[2 * gp][0], stg + OFF_BLO + boff);
            }
            // pass-reordered: per-acc order hh -> hl -> lh (bit-identical),
            // each acc revisited after 15 independent MMAs.
#pragma unroll
            for (int f = 0; f < 2; f++)
#pragma unroll
                for (int g = 0; g < 8; g++)
                    mma_bf16(acc[f][g], ah[f], bh[g]);
#pragma unroll
            for (int f = 0; f < 2; f++)
#pragma unroll
                for (int g = 0; g < 8; g++)
                    mma_bf16(acc[f][g], ah[f], bl[g]);
#pragma unroll
            for (int f = 0; f < 2; f++)
#pragma unroll
                for (int g = 0; g < 8; g++)
                    mma_bf16(acc[f][g], al[f], bh[g]);
        }
    }

#pragma unroll
    for (int g = 0; g < 8; g++) {
        int col0 = colBase + warp_n * 64 + g * 8 + (lane & 3) * 2;
        float2 bb = *reinterpret_cast<const float2*>(&bias[col0]);
#pragma unroll
        for (int f = 0; f < 2; f++) {
            int r0 = rowBase + warp_m * 32 + f * 16 + group;
            float v0 = acc[f][g][0] + bb.x, v1 = acc[f][g][1] + bb.y;
            float v2 = acc[f][g][2] + bb.x, v3 = acc[f][g][3] + bb.y;
            if (OSPLIT) {
                *reinterpret_cast<uint32_t*>(&Chi[(size_t)r0 * DIM + col0]) =
                    pack_bf16x2(v0, v1);
                *reinterpret_cast<uint32_t*>(&Clo[(size_t)r0 * DIM + col0]) =
                    pack_bf16x2(bf16_residual(v0), bf16_residual(v1));
                *reinterpret_cast<uint32_t*>(&Chi[(size_t)(r0 + 8) * DIM + col0]) =
                    pack_bf16x2(v2, v3);
                *reinterpret_cast<uint32_t*>(&Clo[(size_t)(r0 + 8) * DIM + col0]) =
                    pack_bf16x2(bf16_residual(v2), bf16_residual(v3));
            } else {
                *reinterpret_cast<float2*>(&C[(size_t)r0 * DIM + col0]) =
                    make_float2(v0, v1);
                *reinterpret_cast<float2*>(&C[(size_t)(r0 + 8) * DIM + col0]) =
                    make_float2(v2, v3);
            }
        }
    }
}

// ---------------------------------------------------------------------------
// Tensor-core flash attention, register-resident P; MMA pass-reordered in
// 4-wide blocks (dep distance 4) in both S and PV loops (bit-identical).
// ---------------------------------------------------------------------------
#define ATQ 128
#define ATK 64
#define ASHB 144                        // smem row stride bytes (72 bf16)
#define AQ_H 0
#define AQ_L (ATQ * ASHB)               // 18432
#define AST0 (2 * ATQ * ASHB)           // 36864
#define ASTAGE_BYTES (4 * ATK * ASHB)   // 36864 (kh,kl,vth,vtl)
#define AK_H 0
#define AK_L (ATK * ASHB)
#define AV_H (2 * ATK * ASHB)
#define AV_L (3 * ATK * ASHB)
#define AMSK (AST0 + 2 * ASTAGE_BYTES)  // 110592, 2 x 64 floats
#define ATTN_SMEM (AMSK + 2 * 256)      // 111104

__device__ __forceinline__ void attn_load_stage(
    uint32_t sbase,
    const __nv_bfloat16* kh, const __nv_bfloat16* kl,
    const __nv_bfloat16* vth, const __nv_bfloat16* vtl,
    const unsigned char* mk,
    int b, int hcol, int kb, int t) {
    const uint32_t sdst = sbase + AST0 + (uint32_t)(kb & 1) * ASTAGE_BYTES;
    const uint32_t smsk = sbase + AMSK + (uint32_t)(kb & 1) * 256;
    const int keyBase = b * SLEN + kb * ATK;
    const int vtBase  = b * SLEN + hcol;
    const int vtCol   = kb * ATK;
#pragma unroll
    for (int i = 0; i < 2; i++) {
        int id = t + 256 * i;
        int row = id >> 3;
        int c = id & 7;
        uint32_t soff = (uint32_t)(row * ASHB + c * 16);
        cp16(sdst + AK_H + soff,
             kh + (size_t)(keyBase + row) * DIM + hcol + c * 8);
        cp16(sdst + AK_L + soff,
             kl + (size_t)(keyBase + row) * DIM + hcol + c * 8);
        cp16(sdst + AV_H + soff,
             vth + (size_t)(vtBase + row) * SLEN + vtCol + c * 8);
        cp16(sdst + AV_L + soff,
             vtl + (size_t)(vtBase + row) * SLEN + vtCol + c * 8);
    }
    if (t < ATK) {
        float add = mk[b * SLEN + kb * ATK + t] ? -1e30f : 0.0f;
        asm volatile("st.shared.f32 [%0], %1;" :: "r"(smsk + t * 4), "f"(add));
    }
    cp_commit();
}

__global__ __launch_bounds__(256, 2)
void attn_mma_kernel(const __nv_bfloat16* __restrict__ qh,
                     const __nv_bfloat16* __restrict__ ql,
                     const __nv_bfloat16* __restrict__ kh,
                     const __nv_bfloat16* __restrict__ kl,
                     const __nv_bfloat16* __restrict__ vth,
                     const __nv_bfloat16* __restrict__ vtl,
                     const unsigned char* __restrict__ mk,
                     __nv_bfloat16* __restrict__ Oh,
                     __nv_bfloat16* __restrict__ Ol) {
    extern __shared__ __align__(128) unsigned char smem[];
    const uint32_t sbase = smem_u32(smem);

    const int t = threadIdx.x;
    const int lane = t & 31;
    const int w = t >> 5;
    const int group = lane >> 2;
    const int tc4 = (lane & 3) * 4;

    const int qb = blockIdx.x;
    const int h  = blockIdx.y;
    const int b  = blockIdx.z;
    const int qBase = b * SLEN + qb * ATQ;
    const int hcol  = h * HD;

    const float qscale = 0.125f * 1.44269504088896340736f;

#pragma unroll
    for (int i = 0; i < 4; i++) {
        int id = t + 256 * i;
        int row = id >> 3;
        int c = id & 7;
        uint32_t soff = (uint32_t)(row * ASHB + c * 16);
        cp16(sbase + AQ_H + soff, qh + (size_t)(qBase + row) * DIM + hcol + c * 8);
        cp16(sbase + AQ_L + soff, ql + (size_t)(qBase + row) * DIM + hcol + c * 8);
    }
    cp_commit();
    attn_load_stage(sbase, kh, kl, vth, vtl, mk, b, hcol, 0, t);
    attn_load_stage(sbase, kh, kl, vth, vtl, mk, b, hcol, 1, t);

    float o[8][4];
    float m_i[2], l_i[2];
#pragma unroll
    for (int g = 0; g < 8; g++)
#pragma unroll
        for (int r = 0; r < 4; r++) o[g][r] = 0.0f;
    m_i[0] = m_i[1] = -1e30f;
    l_i[0] = l_i[1] = 0.0f;

    const int NT = SLEN / ATK;   // 16
    for (int kb = 0; kb < NT; kb++) {
        if (kb == NT - 1) cp_wait<0>(); else cp_wait<1>();
        __syncthreads();

        const unsigned char* stg = smem + AST0 + (kb & 1) * ASTAGE_BYTES;
        const unsigned char* pKh = stg + AK_H;
        const unsigned char* pKl = stg + AK_L;
        const unsigned char* pVh = stg + AV_H;
        const unsigned char* pVl = stg + AV_L;
        const float* madd =
            reinterpret_cast<const float*>(smem + AMSK + (kb & 1) * 256);

        float s[8][4];
#pragma unroll
        for (int g = 0; g < 8; g++)
#pragma unroll
            for (int r = 0; r < 4; r++) s[g][r] = 0.0f;

        const unsigned char* pQh = smem + AQ_H;
        const unsigned char* pQl = smem + AQ_L;
#pragma unroll
        for (int k = 0; k < 4; k++) {
            const int cb = tc4 + k * 32;
            uint32_t ah[4], al[4];
            int abase = (w * 16 + group) * ASHB + cb;
            ah[0] = *(const uint32_t*)(pQh + abase);
            ah[1] = *(const uint32_t*)(pQh + abase + 8 * ASHB);
            ah[2] = *(const uint32_t*)(pQh + abase + 16);
            ah[3] = *(const uint32_t*)(pQh + abase + 8 * ASHB + 16);
            al[0] = *(const uint32_t*)(pQl + abase);
            al[1] = *(const uint32_t*)(pQl + abase + 8 * ASHB);
            al[2] = *(const uint32_t*)(pQl + abase + 16);
            al[3] = *(const uint32_t*)(pQl + abase + 8 * ASHB + 16);
            // 4-wide blocks, pass-major: dep distance 4 per accumulator
#pragma unroll
            for (int gb = 0; gb < 2; gb++) {
                uint32_t bh[4][2], bl[4][2];
#pragma unroll
                for (int j = 0; j < 4; j++) {
                    int bbase = ((gb * 4 + j) * 8 + group) * ASHB + cb;
                    bh[j][0] = *(const uint32_t*)(pKh + bbase);
                    bh[j][1] = *(const uint32_t*)(pKh + bbase + 16);
                    bl[j][0] = *(const uint32_t*)(pKl + bbase);
                    bl[j][1] = *(const uint32_t*)(pKl + bbase + 16);
                }
#pragma unroll
                for (int j = 0; j < 4; j++) mma_bf16(s[gb * 4 + j], ah, bh[j]);
#pragma unroll
                for (int j = 0; j < 4; j++) mma_bf16(s[gb * 4 + j], ah, bl[j]);
#pragma unroll
                for (int j = 0; j < 4; j++) mma_bf16(s[gb * 4 + j], al, bh[j]);
            }
        }

#pragma unroll
        for (int g = 0; g < 8; g++) {
            float2 ma = *reinterpret_cast<const float2*>(
                &madd[g * 8 + (lane & 3) * 2]);
            s[g][0] = fmaf(s[g][0], qscale, ma.x);
            s[g][1] = fmaf(s[g][1], qscale, ma.y);
            s[g][2] = fmaf(s[g][2], qscale, ma.x);
            s[g][3] = fmaf(s[g][3], qscale, ma.y);
        }
        float mx0 = -1e30f, mx1 = -1e30f;
#pragma unroll
        for (int g = 0; g < 8; g++) {
            mx0 = fmaxf(mx0, fmaxf(s[g][0], s[g][1]));
            mx1 = fmaxf(mx1, fmaxf(s[g][2], s[g][3]));
        }
        mx0 = fmaxf(mx0, __shfl_xor_sync(0xffffffffu, mx0, 1));
        mx0 = fmaxf(mx0, __shfl_xor_sync(0xffffffffu, mx0, 2));
        mx1 = fmaxf(mx1, __shfl_xor_sync(0xffffffffu, mx1, 1));
        mx1 = fmaxf(mx1, __shfl_xor_sync(0xffffffffu, mx1, 2));
        float mn0 = fmaxf(m_i[0], mx0);
        float mn1 = fmaxf(m_i[1], mx1);
        float corr0 = exp2f(m_i[0] - mn0);
        float corr1 = exp2f(m_i[1] - mn1);
        m_i[0] = mn0; m_i[1] = mn1;

        uint32_t pah[4][4], pal[4][4];
        float sum0 = 0.0f, sum1 = 0.0f;
#pragma unroll
        for (int g = 0; g < 8; g++) {
            float p0 = exp2f(s[g][0] - mn0);
            float p1 = exp2f(s[g][1] - mn0);
            float p2 = exp2f(s[g][2] - mn1);
            float p3 = exp2f(s[g][3] - mn1);
            sum0 += p0 + p1;
            sum1 += p2 + p3;
            const int kc = g >> 1;
            const int o2 = (g & 1) * 2;
            pah[kc][o2 + 0] = pack_bf16x2(p0, p1);
            pah[kc][o2 + 1] = pack_bf16x2(p2, p3);
            pal[kc][o2 + 0] = pack_bf16x2(bf16_residual(p0), bf16_residual(p1));
            pal[kc][o2 + 1] = pack_bf16x2(bf16_residual(p2), bf16_residual(p3));
        }
        sum0 += __shfl_xor_sync(0xffffffffu, sum0, 1);
        sum0 += __shfl_xor_sync(0xffffffffu, sum0, 2);
        sum1 += __shfl_xor_sync(0xffffffffu, sum1, 1);
        sum1 += __shfl_xor_sync(0xffffffffu, sum1, 2);
        l_i[0] = l_i[0] * corr0 + sum0;
        l_i[1] = l_i[1] * corr1 + sum1;
#pragma unroll
        for (int g = 0; g < 8; g++) {
            o[g][0] *= corr0; o[g][1] *= corr0;
            o[g][2] *= corr1; o[g][3] *= corr1;
        }

        // PV: 4-wide blocks, pass-major (dep distance 4)
#pragma unroll
        for (int kc = 0; kc < 4; kc++) {
            const int cb = tc4 + kc * 32;
#pragma unroll
            for (int db = 0; db < 2; db++) {
                uint32_t bh[4][2], bl[4][2];
#pragma unroll
                for (int j = 0; j < 4; j++) {
                    int bbase = ((db * 4 + j) * 8 + group) * ASHB + cb;
                    bh[j][0] = *(const uint32_t*)(pVh + bbase);
                    bh[j][1] = *(const uint32_t*)(pVh + bbase + 16);
                    bl[j][0] = *(const uint32_t*)(pVl + bbase);
                    bl[j][1] = *(const uint32_t*)(pVl + bbase + 16);
                }
#pragma unroll
                for (int j = 0; j < 4; j++)
                    mma_bf16(o[db * 4 + j], pah[kc], bh[j]);
#pragma unroll
                for (int j = 0; j < 4; j++)
                    mma_bf16(o[db * 4 + j], pah[kc], bl[j]);
#pragma unroll
                for (int j = 0; j < 4; j++)
                    mma_bf16(o[db * 4 + j], pal[kc], bh[j]);
            }
        }
        __syncthreads();

        if (kb + 2 < NT)
            attn_load_stage(sbase, kh, kl, vth, vtl, mk, b, hcol, kb + 2, t);
    }

    float inv0 = 1.0f / l_i[0];
    float inv1 = 1.0f / l_i[1];
    const int gr0 = qBase + w * 16 + group;
#pragma unroll
    for (int g = 0; g < 8; g++) {
        int col = hcol + g * 8 + (lane & 3) * 2;
        float v0 = o[g][0] * inv0, v1 = o[g][1] * inv0;
        float v2 = o[g][2] * inv1, v3 = o[g][3] * inv1;
        *reinterpret_cast<uint32_t*>(&Oh[(size_t)gr0 * DIM + col]) =
            pack_bf16x2(v0, v1);
        *reinterpret_cast<uint32_t*>(&Ol[(size_t)gr0 * DIM + col]) =
            pack_bf16x2(bf16_residual(v0), bf16_residual(v1));
        *reinterpret_cast<uint32_t*>(&Oh[(size_t)(gr0 + 8) * DIM + col]) =
            pack_bf16x2(v2, v3);
        *reinterpret_cast<uint32_t*>(&Ol[(size_t)(gr0 + 8) * DIM + col]) =
            pack_bf16x2(bf16_residual(v2), bf16_residual(v3));
    }
}

// ---------------------------------------------------------------------------
// Launcher. Q-projection GEMM at user-launch idx 3 = ncu capture slot:
//   0: split  1: t0  2: t1  3: gemmQ <- capture  4: t2  5: t3
//   6: gemmK  7: gemmV  8: transpose_v  9: attn  10: gemmO
// ---------------------------------------------------------------------------
extern "C" void kernel_launch(void* const* d_in, const int* in_sizes, int n_in,
                              void* d_out, int out_size) {
    (void)in_sizes; (void)n_in; (void)out_size;
    const float* x          = (const float*)d_in[0];
    const unsigned char* mk = (const unsigned char*)d_in[1];
    const float* w[4] = {(const float*)d_in[2], (const float*)d_in[4],
                         (const float*)d_in[6], (const float*)d_in[8]};
    const float* bq = (const float*)d_in[3];
    const float* bk = (const float*)d_in[5];
    const float* bv = (const float*)d_in[7];
    const float* bo = (const float*)d_in[9];
    float* out = (float*)d_out;

    __nv_bfloat16 *xh, *xl, *qhp, *qlp, *khp, *klp, *vhp, *vlp;
    __nv_bfloat16 *vth, *vtl, *ah, *al, *wth, *wtl;
    cudaGetSymbolAddress((void**)&xh, g_x_hi);
    cudaGetSymbolAddress((void**)&xl, g_x_lo);
    cudaGetSymbolAddress((void**)&qhp, g_q_hi);
    cudaGetSymbolAddress((void**)&qlp, g_q_lo);
    cudaGetSymbolAddress((void**)&khp, g_k_hi);
    cudaGetSymbolAddress((void**)&klp, g_k_lo);
    cudaGetSymbolAddress((void**)&vhp, g_v_hi);
    cudaGetSymbolAddress((void**)&vlp, g_v_lo);
    cudaGetSymbolAddress((void**)&vth, g_vt_hi);
    cudaGetSymbolAddress((void**)&vtl, g_vt_lo);
    cudaGetSymbolAddress((void**)&ah, g_a_hi);
    cudaGetSymbolAddress((void**)&al, g_a_lo);
    cudaGetSymbolAddress((void**)&wth, g_wt_hi);
    cudaGetSymbolAddress((void**)&wtl, g_wt_lo);

    const int n4 = M_ROWS * DIM / 4;
    dim3 tgrid(DIM / 32, DIM / 32);

    cudaFuncSetAttribute(mma_gemm_kernel<0>,
                         cudaFuncAttributeMaxDynamicSharedMemorySize, GEMM_SMEM);
    cudaFuncSetAttribute(mma_gemm_kernel<1>,
                         cudaFuncAttributeMaxDynamicSharedMemorySize, GEMM_SMEM);
    cudaFuncSetAttribute(attn_mma_kernel,
                         cudaFuncAttributeMaxDynamicSharedMemorySize, ATTN_SMEM);
    dim3 ggrid(DIM / BN, M_ROWS / BM);

    // idx 0: x split
    split_kernel<<<(n4 + 255) / 256, 256>>>(x, xh, xl, n4);
    // idx 1,2: Q and K weight transposes
    transpose_split_kernel<<<tgrid, dim3(32, 8)>>>(
        w[0], wth + 0 * (size_t)DIM * DIM, wtl + 0 * (size_t)DIM * DIM);
    transpose_split_kernel<<<tgrid, dim3(32, 8)>>>(
        w[1], wth + 1 * (size_t)DIM * DIM, wtl + 1 * (size_t)DIM * DIM);
    // idx 3: Q GEMM  <-- ncu capture target
    mma_gemm_kernel<1><<<ggrid, 256, GEMM_SMEM>>>(
        xh, xl, wth + 0 * (size_t)DIM * DIM, wtl + 0 * (size_t)DIM * DIM, bq,
        nullptr, qhp, qlp);
    // idx 4,5: V and O weight transposes
    transpose_split_kernel<<<tgrid, dim3(32, 8)>>>(
        w[2], wth + 2 * (size_t)DIM * DIM, wtl + 2 * (size_t)DIM * DIM);
    transpose_split_kernel<<<tgrid, dim3(32, 8)>>>(
        w[3], wth + 3 * (size_t)DIM * DIM, wtl + 3 * (size_t)DIM * DIM);
    // idx 6,7: K and V GEMMs
    mma_gemm_kernel<1><<<ggrid, 256, GEMM_SMEM>>>(
        xh, xl, wth + 1 * (size_t)DIM * DIM, wtl + 1 * (size_t)DIM * DIM, bk,
        nullptr, khp, klp);
    mma_gemm_kernel<1><<<ggrid, 256, GEMM_SMEM>>>(
        xh, xl, wth + 2 * (size_t)DIM * DIM, wtl + 2 * (size_t)DIM * DIM, bv,
        nullptr, vhp, vlp);
    // idx 8: V transpose
    transpose_v_kernel<<<dim3(32, 32, 4), dim3(32, 8)>>>(vhp, vlp, vth, vtl);
    // idx 9: attention
    attn_mma_kernel<<<dim3(SLEN / ATQ, NH, 4), 256, ATTN_SMEM>>>(
        qhp, qlp, khp, klp, vth, vtl, mk, ah, al);
    // idx 10: output GEMM
    mma_gemm_kernel<0><<<ggrid, 256, GEMM_SMEM>>>(
        ah, al, wth + 3 * (size_t)DIM * DIM, wtl + 3 * (size_t)DIM * DIM, bo,
        out, nullptr, nullptr);
}

// round 15
// speedup vs baseline: 1.1328x; 1.0068x over previous
#include <cuda_runtime.h>
#include <cuda_bf16.h>
#include <math.h>
#include <stdint.h>

// Problem constants
#define M_ROWS 4096   // B*S
#define DIM    1024   // H
#define SLEN   1024
#define NH     16
#define HD     64
#define NSM    148

// ---------------------------------------------------------------------------
// Scratch (allocation-free rule: __device__ globals)
// ---------------------------------------------------------------------------
__device__ __nv_bfloat16 g_x_hi[M_ROWS * DIM];
__device__ __nv_bfloat16 g_x_lo[M_ROWS * DIM];
__device__ __nv_bfloat16 g_q_hi[M_ROWS * DIM];
__device__ __nv_bfloat16 g_q_lo[M_ROWS * DIM];
__device__ __nv_bfloat16 g_k_hi[M_ROWS * DIM];
__device__ __nv_bfloat16 g_k_lo[M_ROWS * DIM];
__device__ __nv_bfloat16 g_v_hi[M_ROWS * DIM];
__device__ __nv_bfloat16 g_v_lo[M_ROWS * DIM];
__device__ __nv_bfloat16 g_vt_hi[M_ROWS * DIM];   // per-batch transposed V
__device__ __nv_bfloat16 g_vt_lo[M_ROWS * DIM];
__device__ __nv_bfloat16 g_a_hi[M_ROWS * DIM];    // attention output (split)
__device__ __nv_bfloat16 g_a_lo[M_ROWS * DIM];
__device__ __nv_bfloat16 g_wt_hi[4][DIM * DIM];   // transposed+split weights [N][K]
__device__ __nv_bfloat16 g_wt_lo[4][DIM * DIM];

// ---------------------------------------------------------------------------
// helpers
// ---------------------------------------------------------------------------
__device__ __forceinline__ uint32_t smem_u32(const void* p) {
    uint32_t a;
    asm("{ .reg .u64 t; cvta.to.shared.u64 t, %1; cvt.u32.u64 %0, t; }"
        : "=r"(a) : "l"(p));
    return a;
}
__device__ __forceinline__ void cp16(uint32_t dst, const void* src) {
    asm volatile("cp.async.cg.shared.global [%0], [%1], 16;"
                 :: "r"(dst), "l"(src));
}
__device__ __forceinline__ void cp_commit() {
    asm volatile("cp.async.commit_group;");
}
template <int N>
__device__ __forceinline__ void cp_wait() {
    asm volatile("cp.async.wait_group %0;" :: "n"(N));
}

__device__ __forceinline__ void mma_bf16(float* c, const uint32_t* a,
                                         const uint32_t* b) {
    asm volatile(
        "mma.sync.aligned.m16n8k16.row.col.f32.bf16.bf16.f32 "
        "{%0,%1,%2,%3}, {%4,%5,%6,%7}, {%8,%9}, {%0,%1,%2,%3};\n"
        : "+f"(c[0]), "+f"(c[1]), "+f"(c[2]), "+f"(c[3])
        : "r"(a[0]), "r"(a[1]), "r"(a[2]), "r"(a[3]), "r"(b[0]), "r"(b[1]));
}

__device__ __forceinline__ void ldsm4(uint32_t* r, uint32_t addr) {
    asm volatile(
        "ldmatrix.sync.aligned.m8n8.x4.shared.b16 {%0,%1,%2,%3}, [%4];"
        : "=r"(r[0]), "=r"(r[1]), "=r"(r[2]), "=r"(r[3]) : "r"(addr));
}

__device__ __forceinline__ uint32_t pack_bf16x2(float x, float y) {
    __nv_bfloat162 h = __floats2bfloat162_rn(x, y);
    return *reinterpret_cast<uint32_t*>(&h);
}
__device__ __forceinline__ float bf16_residual(float x) {
    return x - __bfloat162float(__float2bfloat16(x));
}

// ---------------------------------------------------------------------------
// Split: x (fp32) -> (hi, lo) bf16
// ---------------------------------------------------------------------------
__global__ void split_kernel(const float* __restrict__ in,
                             __nv_bfloat16* __restrict__ hi,
                             __nv_bfloat16* __restrict__ lo, int n4) {
    int i = blockIdx.x * blockDim.x + threadIdx.x;
    if (i >= n4) return;
    float4 x = reinterpret_cast<const float4*>(in)[i];
    uint32_t* hp = reinterpret_cast<uint32_t*>(hi);
    uint32_t* lp = reinterpret_cast<uint32_t*>(lo);
    hp[2 * i]     = pack_bf16x2(x.x, x.y);
    hp[2 * i + 1] = pack_bf16x2(x.z, x.w);
    lp[2 * i]     = pack_bf16x2(bf16_residual(x.x), bf16_residual(x.y));
    lp[2 * i + 1] = pack_bf16x2(bf16_residual(x.z), bf16_residual(x.w));
}

// ---------------------------------------------------------------------------
// Transpose + split for TWO weights (blockIdx.z selects)
// ---------------------------------------------------------------------------
__global__ void transpose_split2_kernel(const float* __restrict__ W0,
                                        const float* __restrict__ W1,
                                        __nv_bfloat16* __restrict__ t_hi,
                                        __nv_bfloat16* __restrict__ t_lo,
                                        int slot0, int slot1) {
    __shared__ float tile[32][33];
    const int tx = threadIdx.x;
    const int ty = threadIdx.y;
    const int k0 = blockIdx.y * 32;
    const int n0 = blockIdx.x * 32;
    const float* W = blockIdx.z ? W1 : W0;
    const size_t wb = (size_t)(blockIdx.z ? slot1 : slot0) * DIM * DIM;
#pragma unroll
    for (int i = 0; i < 4; i++)
        tile[ty + 8 * i][tx] = W[(size_t)(k0 + ty + 8 * i) * DIM + n0 + tx];
    __syncthreads();
#pragma unroll
    for (int i = 0; i < 4; i++) {
        float v = tile[tx][ty + 8 * i];
        size_t o = wb + (size_t)(n0 + ty + 8 * i) * DIM + k0 + tx;
        t_hi[o] = __float2bfloat16(v);
        t_lo[o] = __float2bfloat16(bf16_residual(v));
    }
}

// ---------------------------------------------------------------------------
// Per-batch bf16 transpose: vt[b*1024 + col][s] = v[b*1024 + s][col]
// ---------------------------------------------------------------------------
__global__ void transpose_v_kernel(const __nv_bfloat16* __restrict__ vh,
                                   const __nv_bfloat16* __restrict__ vl,
                                   __nv_bfloat16* __restrict__ th,
                                   __nv_bfloat16* __restrict__ tl) {
    __shared__ __nv_bfloat16 tileh[32][33];
    __shared__ __nv_bfloat16 tilel[32][33];
    const int tx = threadIdx.x;
    const int ty = threadIdx.y;
    const int c0 = blockIdx.x * 32;
    const int s0 = blockIdx.y * 32;
    const int b  = blockIdx.z;
    const size_t base = (size_t)b * SLEN * DIM;
#pragma unroll
    for (int i = 0; i < 4; i++) {
        int s = s0 + ty + 8 * i;
        tileh[ty + 8 * i][tx] = vh[base + (size_t)s * DIM + c0 + tx];
        tilel[ty + 8 * i][tx] = vl[base + (size_t)s * DIM + c0 + tx];
    }
    __syncthreads();
#pragma unroll
    for (int i = 0; i < 4; i++) {
        int c = c0 + ty + 8 * i;
        th[base + (size_t)c * SLEN + s0 + tx] = tileh[tx][ty + 8 * i];
        tl[base + (size_t)c * SLEN + s0 + tx] = tilel[tx][ty + 8 * i];
    }
}

// ---------------------------------------------------------------------------
// bf16x3 tensor-core GEMM tile body (R13-proven):
// ldmatrix.x4; 2-stage single-sync cp.async pipeline; pass-reordered MMAs.
// ---------------------------------------------------------------------------
#define BM 128
#define BN 128
#define BK 32
#define SH 40
#define SHB (SH * 2)                      // 80-byte smem row stride
#define MAT_BYTES (128 * SHB)
#define STAGE_BYTES (4 * MAT_BYTES)       // 40960
#define NSTAGE 2
#define GEMM_SMEM (NSTAGE * STAGE_BYTES)  // 81920 -> 2 CTAs/SM
#define OFF_AHI 0
#define OFF_ALO MAT_BYTES
#define OFF_BHI (2 * MAT_BYTES)
#define OFF_BLO (3 * MAT_BYTES)

__device__ __forceinline__ void load_stage(uint32_t sdst,
                                           const __nv_bfloat16* __restrict__ A_hi,
                                           const __nv_bfloat16* __restrict__ A_lo,
                                           const __nv_bfloat16* __restrict__ B_hi,
                                           const __nv_bfloat16* __restrict__ B_lo,
                                           int rowBase, int colBase, int k0,
                                           int t) {
#pragma unroll
    for (int i = 0; i < 2; i++) {
        int id = t + 256 * i;
        int row = id >> 2;
        int c = id & 3;
        uint32_t soff = (uint32_t)(row * SHB + c * 16);
        const __nv_bfloat16* ah = A_hi + (size_t)(rowBase + row) * DIM + k0 + c * 8;
        const __nv_bfloat16* al = A_lo + (size_t)(rowBase + row) * DIM + k0 + c * 8;
        const __nv_bfloat16* bh = B_hi + (size_t)(colBase + row) * DIM + k0 + c * 8;
        const __nv_bfloat16* bl = B_lo + (size_t)(colBase + row) * DIM + k0 + c * 8;
        cp16(sdst + OFF_AHI + soff, ah);
        cp16(sdst + OFF_ALO + soff, al);
        cp16(sdst + OFF_BHI + soff, bh);
        cp16(sdst + OFF_BLO + soff, bl);
    }
    cp_commit();
}

template <int OSPLIT>
__device__ __forceinline__ void gemm_tile_body(
    uint32_t sbase,
    const __nv_bfloat16* __restrict__ A_hi, const __nv_bfloat16* __restrict__ A_lo,
    const __nv_bfloat16* __restrict__ B_hi, const __nv_bfloat16* __restrict__ B_lo,
    const float* __restrict__ bias, float* __restrict__ C,
    __nv_bfloat16* __restrict__ Chi, __nv_bfloat16* __restrict__ Clo,
    int rowBase, int colBase, int t) {
    const int lane = t & 31;
    const int wid = t >> 5;
    const int warp_m = wid & 3;
    const int warp_n = wid >> 2;
    const int group = lane >> 2;

    const int lr = lane & 7;
    const int lm = lane >> 3;
    const int aRowOff = (warp_m * 32 + ((lm & 1) << 3) + lr) * SHB;
    const int aColOff = (lm >> 1) * 16;
    const int bRowOff = (warp_n * 64 + ((lm >> 1) << 3) + lr) * SHB;
    const int bColOff = (lm & 1) * 16;

    float acc[2][8][4];
#pragma unroll
    for (int f = 0; f < 2; f++)
#pragma unroll
        for (int g = 0; g < 8; g++)
#pragma unroll
            for (int r = 0; r < 4; r++) acc[f][g][r] = 0.0f;

    load_stage(sbase, A_hi, A_lo, B_hi, B_lo, rowBase, colBase, 0, t);

    const int NCHUNK = DIM / BK;   // 32
    for (int c = 0; c < NCHUNK; c++) {
        cp_wait<0>();
        __syncthreads();

        if (c + 1 < NCHUNK)
            load_stage(sbase + (uint32_t)(((c + 1) & 1) * STAGE_BYTES),
                       A_hi, A_lo, B_hi, B_lo, rowBase, colBase,
                       (c + 1) * BK, t);

        const uint32_t stg = sbase + (uint32_t)((c & 1) * STAGE_BYTES);

#pragma unroll
        for (int ks = 0; ks < 2; ks++) {
            const int kcb = ks * 32;
            uint32_t ah[2][4], al[2][4], bh[8][2], bl[8][2];
#pragma unroll
            for (int f = 0; f < 2; f++) {
                uint32_t aoff = (uint32_t)(aRowOff + f * 16 * SHB + kcb + aColOff);
                ldsm4(ah[f], stg + OFF_AHI + aoff);
                ldsm4(al[f], stg + OFF_ALO + aoff);
            }
#pragma unroll
            for (int gp = 0; gp < 4; gp++) {
                uint32_t boff = (uint32_t)(bRowOff + gp * 16 * SHB + kcb + bColOff);
                ldsm4(&bh[2 * gp][0], stg + OFF_BHI + boff);
                ldsm4(&bl[2 * gp][0], stg + OFF_BLO + boff);
            }
#pragma unroll
            for (int f = 0; f < 2; f++)
#pragma unroll
                for (int g = 0; g < 8; g++)
                    mma_bf16(acc[f][g], ah[f], bh[g]);
#pragma unroll
            for (int f = 0; f < 2; f++)
#pragma unroll
                for (int g = 0; g < 8; g++)
                    mma_bf16(acc[f][g], ah[f], bl[g]);
#pragma unroll
            for (int f = 0; f < 2; f++)
#pragma unroll
                for (int g = 0; g < 8; g++)
                    mma_bf16(acc[f][g], al[f], bh[g]);
        }
    }

#pragma unroll
    for (int g = 0; g < 8; g++) {
        int col0 = colBase + warp_n * 64 + g * 8 + (lane & 3) * 2;
        float2 bb = *reinterpret_cast<const float2*>(&bias[col0]);
#pragma unroll
        for (int f = 0; f < 2; f++) {
            int r0 = rowBase + warp_m * 32 + f * 16 + group;
            float v0 = acc[f][g][0] + bb.x, v1 = acc[f][g][1] + bb.y;
            float v2 = acc[f][g][2] + bb.x, v3 = acc[f][g][3] + bb.y;
            if (OSPLIT) {
                *reinterpret_cast<uint32_t*>(&Chi[(size_t)r0 * DIM + col0]) =
                    pack_bf16x2(v0, v1);
                *reinterpret_cast<uint32_t*>(&Clo[(size_t)r0 * DIM + col0]) =
                    pack_bf16x2(bf16_residual(v0), bf16_residual(v1));
                *reinterpret_cast<uint32_t*>(&Chi[(size_t)(r0 + 8) * DIM + col0]) =
                    pack_bf16x2(v2, v3);
                *reinterpret_cast<uint32_t*>(&Clo[(size_t)(r0 + 8) * DIM + col0]) =
                    pack_bf16x2(bf16_residual(v2), bf16_residual(v3));
            } else {
                *reinterpret_cast<float2*>(&C[(size_t)r0 * DIM + col0]) =
                    make_float2(v0, v1);
                *reinterpret_cast<float2*>(&C[(size_t)(r0 + 8) * DIM + col0]) =
                    make_float2(v2, v3);
            }
        }
    }
}

// Persistent merged Q/K/V projection GEMM: 768 tiles over 296 CTAs (2/SM).
__global__ __launch_bounds__(256, 2)
void qkv_gemm_kernel(const __nv_bfloat16* __restrict__ xh,
                     const __nv_bfloat16* __restrict__ xl,
                     const __nv_bfloat16* __restrict__ wth,
                     const __nv_bfloat16* __restrict__ wtl,
                     const float* __restrict__ bq, const float* __restrict__ bk,
                     const float* __restrict__ bv,
                     __nv_bfloat16* __restrict__ qh, __nv_bfloat16* __restrict__ ql,
                     __nv_bfloat16* __restrict__ kh, __nv_bfloat16* __restrict__ kl,
                     __nv_bfloat16* __restrict__ vh, __nv_bfloat16* __restrict__ vl) {
    extern __shared__ __align__(128) unsigned char smem[];
    const uint32_t sbase = smem_u32(smem);
    const int t = threadIdx.x;
    const int NT_PER = (M_ROWS / BM) * (DIM / BN);   // 256
    for (int tile = blockIdx.x; tile < 3 * NT_PER; tile += gridDim.x) {
        int which = tile / NT_PER;
        int rem = tile % NT_PER;
        int rowBase = (rem >> 3) * BM;
        int colBase = (rem & 7) * BN;
        const __nv_bfloat16* Bh = wth + (size_t)which * DIM * DIM;
        const __nv_bfloat16* Bl = wtl + (size_t)which * DIM * DIM;
        const float* bias;
        __nv_bfloat16 *Chi, *Clo;
        if (which == 0)      { bias = bq; Chi = qh; Clo = ql; }
        else if (which == 1) { bias = bk; Chi = kh; Clo = kl; }
        else                 { bias = bv; Chi = vh; Clo = vl; }
        gemm_tile_body<1>(sbase, xh, xl, Bh, Bl, bias, nullptr, Chi, Clo,
                          rowBase, colBase, t);
    }
}

// Output GEMM: plain grid (single GEMM, one wave).
__global__ __launch_bounds__(256, 2)
void out_gemm_kernel(const __nv_bfloat16* __restrict__ ah,
                     const __nv_bfloat16* __restrict__ al,
                     const __nv_bfloat16* __restrict__ wth,
                     const __nv_bfloat16* __restrict__ wtl,
                     const float* __restrict__ bo, float* __restrict__ out) {
    extern __shared__ __align__(128) unsigned char smem[];
    const uint32_t sbase = smem_u32(smem);
    gemm_tile_body<0>(sbase, ah, al, wth, wtl, bo, out, nullptr, nullptr,
                      blockIdx.y * BM, blockIdx.x * BN, threadIdx.x);
}

// ---------------------------------------------------------------------------
// Tensor-core flash attention (R13-proven: register P + 4-wide pass reorder)
// ---------------------------------------------------------------------------
#define ATQ 128
#define ATK 64
#define ASHB 144
#define AQ_H 0
#define AQ_L (ATQ * ASHB)
#define AST0 (2 * ATQ * ASHB)
#define ASTAGE_BYTES (4 * ATK * ASHB)
#define AK_H 0
#define AK_L (ATK * ASHB)
#define AV_H (2 * ATK * ASHB)
#define AV_L (3 * ATK * ASHB)
#define AMSK (AST0 + 2 * ASTAGE_BYTES)
#define ATTN_SMEM (AMSK + 2 * 256)      // 111104

__device__ __forceinline__ void attn_load_stage(
    uint32_t sbase,
    const __nv_bfloat16* kh, const __nv_bfloat16* kl,
    const __nv_bfloat16* vth, const __nv_bfloat16* vtl,
    const unsigned char* mk,
    int b, int hcol, int kb, int t) {
    const uint32_t sdst = sbase + AST0 + (uint32_t)(kb & 1) * ASTAGE_BYTES;
    const uint32_t smsk = sbase + AMSK + (uint32_t)(kb & 1) * 256;
    const int keyBase = b * SLEN + kb * ATK;
    const int vtBase  = b * SLEN + hcol;
    const int vtCol   = kb * ATK;
#pragma unroll
    for (int i = 0; i < 2; i++) {
        int id = t + 256 * i;
        int row = id >> 3;
        int c = id & 7;
        uint32_t soff = (uint32_t)(row * ASHB + c * 16);
        cp16(sdst + AK_H + soff,
             kh + (size_t)(keyBase + row) * DIM + hcol + c * 8);
        cp16(sdst + AK_L + soff,
             kl + (size_t)(keyBase + row) * DIM + hcol + c * 8);
        cp16(sdst + AV_H + soff,
             vth + (size_t)(vtBase + row) * SLEN + vtCol + c * 8);
        cp16(sdst + AV_L + soff,
             vtl + (size_t)(vtBase + row) * SLEN + vtCol + c * 8);
    }
    if (t < ATK) {
        float add = mk[b * SLEN + kb * ATK + t] ? -1e30f : 0.0f;
        asm volatile("st.shared.f32 [%0], %1;" :: "r"(smsk + t * 4), "f"(add));
    }
    cp_commit();
}

__global__ __launch_bounds__(256, 2)
void attn_mma_kernel(const __nv_bfloat16* __restrict__ qh,
                     const __nv_bfloat16* __restrict__ ql,
                     const __nv_bfloat16* __restrict__ kh,
                     const __nv_bfloat16* __restrict__ kl,
                     const __nv_bfloat16* __restrict__ vth,
                     const __nv_bfloat16* __restrict__ vtl,
                     const unsigned char* __restrict__ mk,
                     __nv_bfloat16* __restrict__ Oh,
                     __nv_bfloat16* __restrict__ Ol) {
    extern __shared__ __align__(128) unsigned char smem[];
    const uint32_t sbase = smem_u32(smem);

    const int t = threadIdx.x;
    const int lane = t & 31;
    const int w = t >> 5;
    const int group = lane >> 2;
    const int tc4 = (lane & 3) * 4;

    const int qb = blockIdx.x;
    const int h  = blockIdx.y;
    const int b  = blockIdx.z;
    const int qBase = b * SLEN + qb * ATQ;
    const int hcol  = h * HD;

    const float qscale = 0.125f * 1.44269504088896340736f;

#pragma unroll
    for (int i = 0; i < 4; i++) {
        int id = t + 256 * i;
        int row = id >> 3;
        int c = id & 7;
        uint32_t soff = (uint32_t)(row * ASHB + c * 16);
        cp16(sbase + AQ_H + soff, qh + (size_t)(qBase + row) * DIM + hcol + c * 8);
        cp16(sbase + AQ_L + soff, ql + (size_t)(qBase + row) * DIM + hcol + c * 8);
    }
    cp_commit();
    attn_load_stage(sbase, kh, kl, vth, vtl, mk, b, hcol, 0, t);
    attn_load_stage(sbase, kh, kl, vth, vtl, mk, b, hcol, 1, t);

    float o[8][4];
    float m_i[2], l_i[2];
#pragma unroll
    for (int g = 0; g < 8; g++)
#pragma unroll
        for (int r = 0; r < 4; r++) o[g][r] = 0.0f;
    m_i[0] = m_i[1] = -1e30f;
    l_i[0] = l_i[1] = 0.0f;

    const int NT = SLEN / ATK;   // 16
    for (int kb = 0; kb < NT; kb++) {
        if (kb == NT - 1) cp_wait<0>(); else cp_wait<1>();
        __syncthreads();

        const unsigned char* stg = smem + AST0 + (kb & 1) * ASTAGE_BYTES;
        const unsigned char* pKh = stg + AK_H;
        const unsigned char* pKl = stg + AK_L;
        const unsigned char* pVh = stg + AV_H;
        const unsigned char* pVl = stg + AV_L;
        const float* madd =
            reinterpret_cast<const float*>(smem + AMSK + (kb & 1) * 256);

        float s[8][4];
#pragma unroll
        for (int g = 0; g < 8; g++)
#pragma unroll
            for (int r = 0; r < 4; r++) s[g][r] = 0.0f;

        const unsigned char* pQh = smem + AQ_H;
        const unsigned char* pQl = smem + AQ_L;
#pragma unroll
        for (int k = 0; k < 4; k++) {
            const int cb = tc4 + k * 32;
            uint32_t ah[4], al[4];
            int abase = (w * 16 + group) * ASHB + cb;
            ah[0] = *(const uint32_t*)(pQh + abase);
            ah[1] = *(const uint32_t*)(pQh + abase + 8 * ASHB);
            ah[2] = *(const uint32_t*)(pQh + abase + 16);
            ah[3] = *(const uint32_t*)(pQh + abase + 8 * ASHB + 16);
            al[0] = *(const uint32_t*)(pQl + abase);
            al[1] = *(const uint32_t*)(pQl + abase + 8 * ASHB);
            al[2] = *(const uint32_t*)(pQl + abase + 16);
            al[3] = *(const uint32_t*)(pQl + abase + 8 * ASHB + 16);
#pragma unroll
            for (int gb = 0; gb < 2; gb++) {
                uint32_t bh[4][2], bl[4][2];
#pragma unroll
                for (int j = 0; j < 4; j++) {
                    int bbase = ((gb * 4 + j) * 8 + group) * ASHB + cb;
                    bh[j][0] = *(const uint32_t*)(pKh + bbase);
                    bh[j][1] = *(const uint32_t*)(pKh + bbase + 16);
                    bl[j][0] = *(const uint32_t*)(pKl + bbase);
                    bl[j][1] = *(const uint32_t*)(pKl + bbase + 16);
                }
#pragma unroll
                for (int j = 0; j < 4; j++) mma_bf16(s[gb * 4 + j], ah, bh[j]);
#pragma unroll
                for (int j = 0; j < 4; j++) mma_bf16(s[gb * 4 + j], ah, bl[j]);
#pragma unroll
                for (int j = 0; j < 4; j++) mma_bf16(s[gb * 4 + j], al, bh[j]);
            }
        }

#pragma unroll
        for (int g = 0; g < 8; g++) {
            float2 ma = *reinterpret_cast<const float2*>(
                &madd[g * 8 + (lane & 3) * 2]);
            s[g][0] = fmaf(s[g][0], qscale, ma.x);
            s[g][1] = fmaf(s[g][1], qscale, ma.y);
            s[g][2] = fmaf(s[g][2], qscale, ma.x);
            s[g][3] = fmaf(s[g][3], qscale, ma.y);
        }
        float mx0 = -1e30f, mx1 = -1e30f;
#pragma unroll
        for (int g = 0; g < 8; g++) {
            mx0 = fmaxf(mx0, fmaxf(s[g][0], s[g][1]));
            mx1 = fmaxf(mx1, fmaxf(s[g][2], s[g][3]));
        }
        mx0 = fmaxf(mx0, __shfl_xor_sync(0xffffffffu, mx0, 1));
        mx0 = fmaxf(mx0, __shfl_xor_sync(0xffffffffu, mx0, 2));
        mx1 = fmaxf(mx1, __shfl_xor_sync(0xffffffffu, mx1, 1));
        mx1 = fmaxf(mx1, __shfl_xor_sync(0xffffffffu, mx1, 2));
        float mn0 = fmaxf(m_i[0], mx0);
        float mn1 = fmaxf(m_i[1], mx1);
        float corr0 = exp2f(m_i[0] - mn0);
        float corr1 = exp2f(m_i[1] - mn1);
        m_i[0] = mn0; m_i[1] = mn1;

        uint32_t pah[4][4], pal[4][4];
        float sum0 = 0.0f, sum1 = 0.0f;
#pragma unroll
        for (int g = 0; g < 8; g++) {
            float p0 = exp2f(s[g][0] - mn0);
            float p1 = exp2f(s[g][1] - mn0);
            float p2 = exp2f(s[g][2] - mn1);
            float p3 = exp2f(s[g][3] - mn1);
            sum0 += p0 + p1;
            sum1 += p2 + p3;
            const int kc = g >> 1;
            const int o2 = (g & 1) * 2;
            pah[kc][o2 + 0] = pack_bf16x2(p0, p1);
            pah[kc][o2 + 1] = pack_bf16x2(p2, p3);
            pal[kc][o2 + 0] = pack_bf16x2(bf16_residual(p0), bf16_residual(p1));
            pal[kc][o2 + 1] = pack_bf16x2(bf16_residual(p2), bf16_residual(p3));
        }
        sum0 += __shfl_xor_sync(0xffffffffu, sum0, 1);
        sum0 += __shfl_xor_sync(0xffffffffu, sum0, 2);
        sum1 += __shfl_xor_sync(0xffffffffu, sum1, 1);
        sum1 += __shfl_xor_sync(0xffffffffu, sum1, 2);
        l_i[0] = l_i[0] * corr0 + sum0;
        l_i[1] = l_i[1] * corr1 + sum1;
#pragma unroll
        for (int g = 0; g < 8; g++) {
            o[g][0] *= corr0; o[g][1] *= corr0;
            o[g][2] *= corr1; o[g][3] *= corr1;
        }

#pragma unroll
        for (int kc = 0; kc < 4; kc++) {
            const int cb = tc4 + kc * 32;
#pragma unroll
            for (int db = 0; db < 2; db++) {
                uint32_t bh[4][2], bl[4][2];
#pragma unroll
                for (int j = 0; j < 4; j++) {
                    int bbase = ((db * 4 + j) * 8 + group) * ASHB + cb;
                    bh[j][0] = *(const uint32_t*)(pVh + bbase);
                    bh[j][1] = *(const uint32_t*)(pVh + bbase + 16);
                    bl[j][0] = *(const uint32_t*)(pVl + bbase);
                    bl[j][1] = *(const uint32_t*)(pVl + bbase + 16);
                }
#pragma unroll
                for (int j = 0; j < 4; j++)
                    mma_bf16(o[db * 4 + j], pah[kc], bh[j]);
#pragma unroll
                for (int j = 0; j < 4; j++)
                    mma_bf16(o[db * 4 + j], pah[kc], bl[j]);
#pragma unroll
                for (int j = 0; j < 4; j++)
                    mma_bf16(o[db * 4 + j], pal[kc], bh[j]);
            }
        }
        __syncthreads();

        if (kb + 2 < NT)
            attn_load_stage(sbase, kh, kl, vth, vtl, mk, b, hcol, kb + 2, t);
    }

    float inv0 = 1.0f / l_i[0];
    float inv1 = 1.0f / l_i[1];
    const int gr0 = qBase + w * 16 + group;
#pragma unroll
    for (int g = 0; g < 8; g++) {
        int col = hcol + g * 8 + (lane & 3) * 2;
        float v0 = o[g][0] * inv0, v1 = o[g][1] * inv0;
        float v2 = o[g][2] * inv1, v3 = o[g][3] * inv1;
        *reinterpret_cast<uint32_t*>(&Oh[(size_t)gr0 * DIM + col]) =
            pack_bf16x2(v0, v1);
        *reinterpret_cast<uint32_t*>(&Ol[(size_t)gr0 * DIM + col]) =
            pack_bf16x2(bf16_residual(v0), bf16_residual(v1));
        *reinterpret_cast<uint32_t*>(&Oh[(size_t)(gr0 + 8) * DIM + col]) =
            pack_bf16x2(v2, v3);
        *reinterpret_cast<uint32_t*>(&Ol[(size_t)(gr0 + 8) * DIM + col]) =
            pack_bf16x2(bf16_residual(v2), bf16_residual(v3));
    }
}

// ---------------------------------------------------------------------------
// Launcher. Capture slot = user-launch idx 3 (measured):
//   0: t01  1: t23  2: split  3: qkvGemm <- capture
//   4: transpose_v  5: attn  6: gemmO
// ---------------------------------------------------------------------------
extern "C" void kernel_launch(void* const* d_in, const int* in_sizes, int n_in,
                              void* d_out, int out_size) {
    (void)in_sizes; (void)n_in; (void)out_size;
    const float* x          = (const float*)d_in[0];
    const unsigned char* mk = (const unsigned char*)d_in[1];
    const float* w[4] = {(const float*)d_in[2], (const float*)d_in[4],
                         (const float*)d_in[6], (const float*)d_in[8]};
    const float* bq = (const float*)d_in[3];
    const float* bk = (const float*)d_in[5];
    const float* bv = (const float*)d_in[7];
    const float* bo = (const float*)d_in[9];
    float* out = (float*)d_out;

    __nv_bfloat16 *xh, *xl, *qhp, *qlp, *khp, *klp, *vhp, *vlp;
    __nv_bfloat16 *vth, *vtl, *ah, *al, *wth, *wtl;
    cudaGetSymbolAddress((void**)&xh, g_x_hi);
    cudaGetSymbolAddress((void**)&xl, g_x_lo);
    cudaGetSymbolAddress((void**)&qhp, g_q_hi);
    cudaGetSymbolAddress((void**)&qlp, g_q_lo);
    cudaGetSymbolAddress((void**)&khp, g_k_hi);
    cudaGetSymbolAddress((void**)&klp, g_k_lo);
    cudaGetSymbolAddress((void**)&vhp, g_v_hi);
    cudaGetSymbolAddress((void**)&vlp, g_v_lo);
    cudaGetSymbolAddress((void**)&vth, g_vt_hi);
    cudaGetSymbolAddress((void**)&vtl, g_vt_lo);
    cudaGetSymbolAddress((void**)&ah, g_a_hi);
    cudaGetSymbolAddress((void**)&al, g_a_lo);
    cudaGetSymbolAddress((void**)&wth, g_wt_hi);
    cudaGetSymbolAddress((void**)&wtl, g_wt_lo);

    const int n4 = M_ROWS * DIM / 4;
    dim3 tgrid2(DIM / 32, DIM / 32, 2);

    cudaFuncSetAttribute(qkv_gemm_kernel,
                         cudaFuncAttributeMaxDynamicSharedMemorySize, GEMM_SMEM);
    cudaFuncSetAttribute(out_gemm_kernel,
                         cudaFuncAttributeMaxDynamicSharedMemorySize, GEMM_SMEM);
    cudaFuncSetAttribute(attn_mma_kernel,
                         cudaFuncAttributeMaxDynamicSharedMemorySize, ATTN_SMEM);

    // idx 0: W_q + W_k transpose+split
    transpose_split2_kernel<<<tgrid2, dim3(32, 8)>>>(w[0], w[1], wth, wtl, 0, 1);
    // idx 1: W_v + W_o transpose+split
    transpose_split2_kernel<<<tgrid2, dim3(32, 8)>>>(w[2], w[3], wth, wtl, 2, 3);
    // idx 2: x split
    split_kernel<<<(n4 + 255) / 256, 256>>>(x, xh, xl, n4);
    // idx 3: merged persistent QKV GEMM  <-- ncu capture target
    qkv_gemm_kernel<<<2 * NSM, 256, GEMM_SMEM>>>(
        xh, xl, wth, wtl, bq, bk, bv, qhp, qlp, khp, klp, vhp, vlp);
    // idx 4: V transpose
    transpose_v_kernel<<<dim3(32, 32, 4), dim3(32, 8)>>>(vhp, vlp, vth, vtl);
    // idx 5: attention
    attn_mma_kernel<<<dim3(SLEN / ATQ, NH, 4), 256, ATTN_SMEM>>>(
        qhp, qlp, khp, klp, vth, vtl, mk, ah, al);
    // idx 6: output GEMM
    out_gemm_kernel<<<dim3(DIM / BN, M_ROWS / BM), 256, GEMM_SMEM>>>(
        ah, al, wth + 3 * (size_t)DIM * DIM, wtl + 3 * (size_t)DIM * DIM, bo, out);
}

// round 17
// speedup vs baseline: 1.1432x; 1.0092x over previous
#include <cuda_runtime.h>
#include <cuda_bf16.h>
#include <math.h>
#include <stdint.h>

// Problem constants
#define M_ROWS 4096   // B*S
#define DIM    1024   // H
#define SLEN   1024
#define NH     16
#define HD     64
#define NSM    148

// ---------------------------------------------------------------------------
// Scratch (allocation-free rule: __device__ globals)
// ---------------------------------------------------------------------------
__device__ __nv_bfloat16 g_x_hi[M_ROWS * DIM];
__device__ __nv_bfloat16 g_x_lo[M_ROWS * DIM];
__device__ __nv_bfloat16 g_q_hi[M_ROWS * DIM];
__device__ __nv_bfloat16 g_q_lo[M_ROWS * DIM];
__device__ __nv_bfloat16 g_k_hi[M_ROWS * DIM];
__device__ __nv_bfloat16 g_k_lo[M_ROWS * DIM];
__device__ __nv_bfloat16 g_v_hi[M_ROWS * DIM];
__device__ __nv_bfloat16 g_v_lo[M_ROWS * DIM];
__device__ __nv_bfloat16 g_vt_hi[M_ROWS * DIM];   // per-batch transposed V
__device__ __nv_bfloat16 g_vt_lo[M_ROWS * DIM];
__device__ __nv_bfloat16 g_a_hi[M_ROWS * DIM];    // attention output (split)
__device__ __nv_bfloat16 g_a_lo[M_ROWS * DIM];
__device__ __nv_bfloat16 g_wt_hi[4][DIM * DIM];   // transposed+split weights [N][K]
__device__ __nv_bfloat16 g_wt_lo[4][DIM * DIM];

// ---------------------------------------------------------------------------
// helpers
// ---------------------------------------------------------------------------
__device__ __forceinline__ uint32_t smem_u32(const void* p) {
    uint32_t a;
    asm("{ .reg .u64 t; cvta.to.shared.u64 t, %1; cvt.u32.u64 %0, t; }"
        : "=r"(a) : "l"(p));
    return a;
}
__device__ __forceinline__ void cp16(uint32_t dst, const void* src) {
    asm volatile("cp.async.cg.shared.global [%0], [%1], 16;"
                 :: "r"(dst), "l"(src));
}
__device__ __forceinline__ void cp_commit() {
    asm volatile("cp.async.commit_group;");
}
template <int N>
__device__ __forceinline__ void cp_wait() {
    asm volatile("cp.async.wait_group %0;" :: "n"(N));
}

__device__ __forceinline__ void mma_bf16(float* c, const uint32_t* a,
                                         const uint32_t* b) {
    asm volatile(
        "mma.sync.aligned.m16n8k16.row.col.f32.bf16.bf16.f32 "
        "{%0,%1,%2,%3}, {%4,%5,%6,%7}, {%8,%9}, {%0,%1,%2,%3};\n"
        : "+f"(c[0]), "+f"(c[1]), "+f"(c[2]), "+f"(c[3])
        : "r"(a[0]), "r"(a[1]), "r"(a[2]), "r"(a[3]), "r"(b[0]), "r"(b[1]));
}

__device__ __forceinline__ void ldsm4(uint32_t* r, uint32_t addr) {
    asm volatile(
        "ldmatrix.sync.aligned.m8n8.x4.shared.b16 {%0,%1,%2,%3}, [%4];"
        : "=r"(r[0]), "=r"(r[1]), "=r"(r[2]), "=r"(r[3]) : "r"(addr));
}

__device__ __forceinline__ uint32_t pack_bf16x2(float x, float y) {
    __nv_bfloat162 h = __floats2bfloat162_rn(x, y);
    return *reinterpret_cast<uint32_t*>(&h);
}
__device__ __forceinline__ float bf16_residual(float x) {
    return x - __bfloat162float(__float2bfloat16(x));
}

// ---------------------------------------------------------------------------
// Merged prep: blocks [0,4096) split x; blocks [4096,8192) transpose+split
// the 4 weight matrices (1024 blocks each).
// ---------------------------------------------------------------------------
__global__ void prep_kernel(const float* __restrict__ x,
                            const float* __restrict__ w0,
                            const float* __restrict__ w1,
                            const float* __restrict__ w2,
                            const float* __restrict__ w3,
                            __nv_bfloat16* __restrict__ xh,
                            __nv_bfloat16* __restrict__ xl,
                            __nv_bfloat16* __restrict__ t_hi,
                            __nv_bfloat16* __restrict__ t_lo) {
    const int bid = blockIdx.x;
    const int tid = threadIdx.x;
    if (bid < 4096) {
        // split: 4 fp32 per thread
        int i = bid * 256 + tid;            // float4 index, n4 = 1048576
        float4 v = reinterpret_cast<const float4*>(x)[i];
        uint32_t* hp = reinterpret_cast<uint32_t*>(xh);
        uint32_t* lp = reinterpret_cast<uint32_t*>(xl);
        hp[2 * i]     = pack_bf16x2(v.x, v.y);
        hp[2 * i + 1] = pack_bf16x2(v.z, v.w);
        lp[2 * i]     = pack_bf16x2(bf16_residual(v.x), bf16_residual(v.y));
        lp[2 * i + 1] = pack_bf16x2(bf16_residual(v.z), bf16_residual(v.w));
    } else {
        __shared__ float tile[32][33];
        const int r = bid - 4096;
        const int widx = r >> 10;           // 0..3
        const int tl32 = r & 1023;
        const int n0 = (tl32 & 31) * 32;
        const int k0 = (tl32 >> 5) * 32;
        const float* W = (widx == 0) ? w0 : (widx == 1) ? w1
                       : (widx == 2) ? w2 : w3;
        const size_t wb = (size_t)widx * DIM * DIM;
        const int tx = tid & 31;
        const int ty = tid >> 5;            // 0..7
#pragma unroll
        for (int i = 0; i < 4; i++)
            tile[ty + 8 * i][tx] = W[(size_t)(k0 + ty + 8 * i) * DIM + n0 + tx];
        __syncthreads();
#pragma unroll
        for (int i = 0; i < 4; i++) {
            float v = tile[tx][ty + 8 * i];
            size_t o = wb + (size_t)(n0 + ty + 8 * i) * DIM + k0 + tx;
            t_hi[o] = __float2bfloat16(v);
            t_lo[o] = __float2bfloat16(bf16_residual(v));
        }
    }
}

// ---------------------------------------------------------------------------
// Per-batch bf16 transpose: vt[b*1024 + col][s] = v[b*1024 + s][col]
// ---------------------------------------------------------------------------
__global__ void transpose_v_kernel(const __nv_bfloat16* __restrict__ vh,
                                   const __nv_bfloat16* __restrict__ vl,
                                   __nv_bfloat16* __restrict__ th,
                                   __nv_bfloat16* __restrict__ tl) {
    __shared__ __nv_bfloat16 tileh[32][33];
    __shared__ __nv_bfloat16 tilel[32][33];
    const int tx = threadIdx.x;
    const int ty = threadIdx.y;
    const int c0 = blockIdx.x * 32;
    const int s0 = blockIdx.y * 32;
    const int b  = blockIdx.z;
    const size_t base = (size_t)b * SLEN * DIM;
#pragma unroll
    for (int i = 0; i < 4; i++) {
        int s = s0 + ty + 8 * i;
        tileh[ty + 8 * i][tx] = vh[base + (size_t)s * DIM + c0 + tx];
        tilel[ty + 8 * i][tx] = vl[base + (size_t)s * DIM + c0 + tx];
    }
    __syncthreads();
#pragma unroll
    for (int i = 0; i < 4; i++) {
        int c = c0 + ty + 8 * i;
        th[base + (size_t)c * SLEN + s0 + tx] = tileh[tx][ty + 8 * i];
        tl[base + (size_t)c * SLEN + s0 + tx] = tilel[tx][ty + 8 * i];
    }
}

// ---------------------------------------------------------------------------
// bf16x3 tensor-core GEMM tile body (R13-proven):
// ldmatrix.x4; 2-stage single-sync cp.async pipeline; pass-reordered MMAs.
// ---------------------------------------------------------------------------
#define BM 128
#define BN 128
#define BK 32
#define SH 40
#define SHB (SH * 2)                      // 80-byte smem row stride
#define MAT_BYTES (128 * SHB)
#define STAGE_BYTES (4 * MAT_BYTES)       // 40960
#define NSTAGE 2
#define GEMM_SMEM (NSTAGE * STAGE_BYTES)  // 81920 -> 2 CTAs/SM
#define OFF_AHI 0
#define OFF_ALO MAT_BYTES
#define OFF_BHI (2 * MAT_BYTES)
#define OFF_BLO (3 * MAT_BYTES)

__device__ __forceinline__ void load_stage(uint32_t sdst,
                                           const __nv_bfloat16* __restrict__ A_hi,
                                           const __nv_bfloat16* __restrict__ A_lo,
                                           const __nv_bfloat16* __restrict__ B_hi,
                                           const __nv_bfloat16* __restrict__ B_lo,
                                           int rowBase, int colBase, int k0,
                                           int t) {
#pragma unroll
    for (int i = 0; i < 2; i++) {
        int id = t + 256 * i;
        int row = id >> 2;
        int c = id & 3;
        uint32_t soff = (uint32_t)(row * SHB + c * 16);
        const __nv_bfloat16* ah = A_hi + (size_t)(rowBase + row) * DIM + k0 + c * 8;
        const __nv_bfloat16* al = A_lo + (size_t)(rowBase + row) * DIM + k0 + c * 8;
        const __nv_bfloat16* bh = B_hi + (size_t)(colBase + row) * DIM + k0 + c * 8;
        const __nv_bfloat16* bl = B_lo + (size_t)(colBase + row) * DIM + k0 + c * 8;
        cp16(sdst + OFF_AHI + soff, ah);
        cp16(sdst + OFF_ALO + soff, al);
        cp16(sdst + OFF_BHI + soff, bh);
        cp16(sdst + OFF_BLO + soff, bl);
    }
    cp_commit();
}

template <int OSPLIT>
__device__ __forceinline__ void gemm_tile_body(
    uint32_t sbase,
    const __nv_bfloat16* __restrict__ A_hi, const __nv_bfloat16* __restrict__ A_lo,
    const __nv_bfloat16* __restrict__ B_hi, const __nv_bfloat16* __restrict__ B_lo,
    const float* __restrict__ bias, float* __restrict__ C,
    __nv_bfloat16* __restrict__ Chi, __nv_bfloat16* __restrict__ Clo,
    int rowBase, int colBase, int t) {
    const int lane = t & 31;
    const int wid = t >> 5;
    const int warp_m = wid & 3;
    const int warp_n = wid >> 2;
    const int group = lane >> 2;

    const int lr = lane & 7;
    const int lm = lane >> 3;
    const int aRowOff = (warp_m * 32 + ((lm & 1) << 3) + lr) * SHB;
    const int aColOff = (lm >> 1) * 16;
    const int bRowOff = (warp_n * 64 + ((lm >> 1) << 3) + lr) * SHB;
    const int bColOff = (lm & 1) * 16;

    float acc[2][8][4];
#pragma unroll
    for (int f = 0; f < 2; f++)
#pragma unroll
        for (int g = 0; g < 8; g++)
#pragma unroll
            for (int r = 0; r < 4; r++) acc[f][g][r] = 0.0f;

    load_stage(sbase, A_hi, A_lo, B_hi, B_lo, rowBase, colBase, 0, t);

    const int NCHUNK = DIM / BK;   // 32
    for (int c = 0; c < NCHUNK; c++) {
        cp_wait<0>();
        __syncthreads();

        if (c + 1 < NCHUNK)
            load_stage(sbase + (uint32_t)(((c + 1) & 1) * STAGE_BYTES),
                       A_hi, A_lo, B_hi, B_lo, rowBase, colBase,
                       (c + 1) * BK, t);

        const uint32_t stg = sbase + (uint32_t)((c & 1) * STAGE_BYTES);

#pragma unroll
        for (int ks = 0; ks < 2; ks++) {
            const int kcb = ks * 32;
            uint32_t ah[2][4], al[2][4], bh[8][2], bl[8][2];
#pragma unroll
            for (int f = 0; f < 2; f++) {
                uint32_t aoff = (uint32_t)(aRowOff + f * 16 * SHB + kcb + aColOff);
                ldsm4(ah[f], stg + OFF_AHI + aoff);
                ldsm4(al[f], stg + OFF_ALO + aoff);
            }
#pragma unroll
            for (int gp = 0; gp < 4; gp++) {
                uint32_t boff = (uint32_t)(bRowOff + gp * 16 * SHB + kcb + bColOff);
                ldsm4(&bh[2 * gp][0], stg + OFF_BHI + boff);
                ldsm4(&bl[2 * gp][0], stg + OFF_BLO + boff);
            }
#pragma unroll
            for (int f = 0; f < 2; f++)
#pragma unroll
                for (int g = 0; g < 8; g++)
                    mma_bf16(acc[f][g], ah[f], bh[g]);
#pragma unroll
            for (int f = 0; f < 2; f++)
#pragma unroll
                for (int g = 0; g < 8; g++)
                    mma_bf16(acc[f][g], ah[f], bl[g]);
#pragma unroll
            for (int f = 0; f < 2; f++)
#pragma unroll
                for (int g = 0; g < 8; g++)
                    mma_bf16(acc[f][g], al[f], bh[g]);
        }
    }

#pragma unroll
    for (int g = 0; g < 8; g++) {
        int col0 = colBase + warp_n * 64 + g * 8 + (lane & 3) * 2;
        float2 bb = *reinterpret_cast<const float2*>(&bias[col0]);
#pragma unroll
        for (int f = 0; f < 2; f++) {
            int r0 = rowBase + warp_m * 32 + f * 16 + group;
            float v0 = acc[f][g][0] + bb.x, v1 = acc[f][g][1] + bb.y;
            float v2 = acc[f][g][2] + bb.x, v3 = acc[f][g][3] + bb.y;
            if (OSPLIT) {
                *reinterpret_cast<uint32_t*>(&Chi[(size_t)r0 * DIM + col0]) =
                    pack_bf16x2(v0, v1);
                *reinterpret_cast<uint32_t*>(&Clo[(size_t)r0 * DIM + col0]) =
                    pack_bf16x2(bf16_residual(v0), bf16_residual(v1));
                *reinterpret_cast<uint32_t*>(&Chi[(size_t)(r0 + 8) * DIM + col0]) =
                    pack_bf16x2(v2, v3);
                *reinterpret_cast<uint32_t*>(&Clo[(size_t)(r0 + 8) * DIM + col0]) =
                    pack_bf16x2(bf16_residual(v2), bf16_residual(v3));
            } else {
                *reinterpret_cast<float2*>(&C[(size_t)r0 * DIM + col0]) =
                    make_float2(v0, v1);
                *reinterpret_cast<float2*>(&C[(size_t)(r0 + 8) * DIM + col0]) =
                    make_float2(v2, v3);
            }
        }
    }
}

// Persistent merged Q/K/V projection GEMM: 768 tiles over 296 CTAs (2/SM).
__global__ __launch_bounds__(256, 2)
void qkv_gemm_kernel(const __nv_bfloat16* __restrict__ xh,
                     const __nv_bfloat16* __restrict__ xl,
                     const __nv_bfloat16* __restrict__ wth,
                     const __nv_bfloat16* __restrict__ wtl,
                     const float* __restrict__ bq, const float* __restrict__ bk,
                     const float* __restrict__ bv,
                     __nv_bfloat16* __restrict__ qh, __nv_bfloat16* __restrict__ ql,
                     __nv_bfloat16* __restrict__ kh, __nv_bfloat16* __restrict__ kl,
                     __nv_bfloat16* __restrict__ vh, __nv_bfloat16* __restrict__ vl) {
    extern __shared__ __align__(128) unsigned char smem[];
    const uint32_t sbase = smem_u32(smem);
    const int t = threadIdx.x;
    const int NT_PER = (M_ROWS / BM) * (DIM / BN);   // 256
    for (int tile = blockIdx.x; tile < 3 * NT_PER; tile += gridDim.x) {
        int which = tile / NT_PER;
        int rem = tile % NT_PER;
        int rowBase = (rem >> 3) * BM;
        int colBase = (rem & 7) * BN;
        const __nv_bfloat16* Bh = wth + (size_t)which * DIM * DIM;
        const __nv_bfloat16* Bl = wtl + (size_t)which * DIM * DIM;
        const float* bias;
        __nv_bfloat16 *Chi, *Clo;
        if (which == 0)      { bias = bq; Chi = qh; Clo = ql; }
        else if (which == 1) { bias = bk; Chi = kh; Clo = kl; }
        else                 { bias = bv; Chi = vh; Clo = vl; }
        gemm_tile_body<1>(sbase, xh, xl, Bh, Bl, bias, nullptr, Chi, Clo,
                          rowBase, colBase, t);
    }
}

// Output GEMM: plain grid (single GEMM, one wave).
__global__ __launch_bounds__(256, 2)
void out_gemm_kernel(const __nv_bfloat16* __restrict__ ah,
                     const __nv_bfloat16* __restrict__ al,
                     const __nv_bfloat16* __restrict__ wth,
                     const __nv_bfloat16* __restrict__ wtl,
                     const float* __restrict__ bo, float* __restrict__ out) {
    extern __shared__ __align__(128) unsigned char smem[];
    const uint32_t sbase = smem_u32(smem);
    gemm_tile_body<0>(sbase, ah, al, wth, wtl, bo, out, nullptr, nullptr,
                      blockIdx.y * BM, blockIdx.x * BN, threadIdx.x);
}

// ---------------------------------------------------------------------------
// Tensor-core flash attention (R13-proven: register P + 4-wide pass reorder)
// ---------------------------------------------------------------------------
#define ATQ 128
#define ATK 64
#define ASHB 144
#define AQ_H 0
#define AQ_L (ATQ * ASHB)
#define AST0 (2 * ATQ * ASHB)
#define ASTAGE_BYTES (4 * ATK * ASHB)
#define AK_H 0
#define AK_L (ATK * ASHB)
#define AV_H (2 * ATK * ASHB)
#define AV_L (3 * ATK * ASHB)
#define AMSK (AST0 + 2 * ASTAGE_BYTES)
#define ATTN_SMEM (AMSK + 2 * 256)      // 111104

__device__ __forceinline__ void attn_load_stage(
    uint32_t sbase,
    const __nv_bfloat16* kh, const __nv_bfloat16* kl,
    const __nv_bfloat16* vth, const __nv_bfloat16* vtl,
    const unsigned char* mk,
    int b, int hcol, int kb, int t) {
    const uint32_t sdst = sbase + AST0 + (uint32_t)(kb & 1) * ASTAGE_BYTES;
    const uint32_t smsk = sbase + AMSK + (uint32_t)(kb & 1) * 256;
    const int keyBase = b * SLEN + kb * ATK;
    const int vtBase  = b * SLEN + hcol;
    const int vtCol   = kb * ATK;
#pragma unroll
    for (int i = 0; i < 2; i++) {
        int id = t + 256 * i;
        int row = id >> 3;
        int c = id & 7;
        uint32_t soff = (uint32_t)(row * ASHB + c * 16);
        cp16(sdst + AK_H + soff,
             kh + (size_t)(keyBase + row) * DIM + hcol + c * 8);
        cp16(sdst + AK_L + soff,
             kl + (size_t)(keyBase + row) * DIM + hcol + c * 8);
        cp16(sdst + AV_H + soff,
             vth + (size_t)(vtBase + row) * SLEN + vtCol + c * 8);
        cp16(sdst + AV_L + soff,
             vtl + (size_t)(vtBase + row) * SLEN + vtCol + c * 8);
    }
    if (t < ATK) {
        float add = mk[b * SLEN + kb * ATK + t] ? -1e30f : 0.0f;
        asm volatile("st.shared.f32 [%0], %1;" :: "r"(smsk + t * 4), "f"(add));
    }
    cp_commit();
}

__global__ __launch_bounds__(256, 2)
void attn_mma_kernel(const __nv_bfloat16* __restrict__ qh,
                     const __nv_bfloat16* __restrict__ ql,
                     const __nv_bfloat16* __restrict__ kh,
                     const __nv_bfloat16* __restrict__ kl,
                     const __nv_bfloat16* __restrict__ vth,
                     const __nv_bfloat16* __restrict__ vtl,
                     const unsigned char* __restrict__ mk,
                     __nv_bfloat16* __restrict__ Oh,
                     __nv_bfloat16* __restrict__ Ol) {
    extern __shared__ __align__(128) unsigned char smem[];
    const uint32_t sbase = smem_u32(smem);

    const int t = threadIdx.x;
    const int lane = t & 31;
    const int w = t >> 5;
    const int group = lane >> 2;
    const int tc4 = (lane & 3) * 4;

    const int qb = blockIdx.x;
    const int h  = blockIdx.y;
    const int b  = blockIdx.z;
    const int qBase = b * SLEN + qb * ATQ;
    const int hcol  = h * HD;

    const float qscale = 0.125f * 1.44269504088896340736f;

#pragma unroll
    for (int i = 0; i < 4; i++) {
        int id = t + 256 * i;
        int row = id >> 3;
        int c = id & 7;
        uint32_t soff = (uint32_t)(row * ASHB + c * 16);
        cp16(sbase + AQ_H + soff, qh + (size_t)(qBase + row) * DIM + hcol + c * 8);
        cp16(sbase + AQ_L + soff, ql + (size_t)(qBase + row) * DIM + hcol + c * 8);
    }
    cp_commit();
    attn_load_stage(sbase, kh, kl, vth, vtl, mk, b, hcol, 0, t);
    attn_load_stage(sbase, kh, kl, vth, vtl, mk, b, hcol, 1, t);

    float o[8][4];
    float m_i[2], l_i[2];
#pragma unroll
    for (int g = 0; g < 8; g++)
#pragma unroll
        for (int r = 0; r < 4; r++) o[g][r] = 0.0f;
    m_i[0] = m_i[1] = -1e30f;
    l_i[0] = l_i[1] = 0.0f;

    const int NT = SLEN / ATK;   // 16
    for (int kb = 0; kb < NT; kb++) {
        if (kb == NT - 1) cp_wait<0>(); else cp_wait<1>();
        __syncthreads();

        const unsigned char* stg = smem + AST0 + (kb & 1) * ASTAGE_BYTES;
        const unsigned char* pKh = stg + AK_H;
        const unsigned char* pKl = stg + AK_L;
        const unsigned char* pVh = stg + AV_H;
        const unsigned char* pVl = stg + AV_L;
        const float* madd =
            reinterpret_cast<const float*>(smem + AMSK + (kb & 1) * 256);

        float s[8][4];
#pragma unroll
        for (int g = 0; g < 8; g++)
#pragma unroll
            for (int r = 0; r < 4; r++) s[g][r] = 0.0f;

        const unsigned char* pQh = smem + AQ_H;
        const unsigned char* pQl = smem + AQ_L;
#pragma unroll
        for (int k = 0; k < 4; k++) {
            const int cb = tc4 + k * 32;
            uint32_t ah[4], al[4];
            int abase = (w * 16 + group) * ASHB + cb;
            ah[0] = *(const uint32_t*)(pQh + abase);
            ah[1] = *(const uint32_t*)(pQh + abase + 8 * ASHB);
            ah[2] = *(const uint32_t*)(pQh + abase + 16);
            ah[3] = *(const uint32_t*)(pQh + abase + 8 * ASHB + 16);
            al[0] = *(const uint32_t*)(pQl + abase);
            al[1] = *(const uint32_t*)(pQl + abase + 8 * ASHB);
            al[2] = *(const uint32_t*)(pQl + abase + 16);
            al[3] = *(const uint32_t*)(pQl + abase + 8 * ASHB + 16);
#pragma unroll
            for (int gb = 0; gb < 2; gb++) {
                uint32_t bh[4][2], bl[4][2];
#pragma unroll
                for (int j = 0; j < 4; j++) {
                    int bbase = ((gb * 4 + j) * 8 + group) * ASHB + cb;
                    bh[j][0] = *(const uint32_t*)(pKh + bbase);
                    bh[j][1] = *(const uint32_t*)(pKh + bbase + 16);
                    bl[j][0] = *(const uint32_t*)(pKl + bbase);
                    bl[j][1] = *(const uint32_t*)(pKl + bbase + 16);
                }
#pragma unroll
                for (int j = 0; j < 4; j++) mma_bf16(s[gb * 4 + j], ah, bh[j]);
#pragma unroll
                for (int j = 0; j < 4; j++) mma_bf16(s[gb * 4 + j], ah, bl[j]);
#pragma unroll
                for (int j = 0; j < 4; j++) mma_bf16(s[gb * 4 + j], al, bh[j]);
            }
        }

#pragma unroll
        for (int g = 0; g < 8; g++) {
            float2 ma = *reinterpret_cast<const float2*>(
                &madd[g * 8 + (lane & 3) * 2]);
            s[g][0] = fmaf(s[g][0], qscale, ma.x);
            s[g][1] = fmaf(s[g][1], qscale, ma.y);
            s[g][2] = fmaf(s[g][2], qscale, ma.x);
            s[g][3] = fmaf(s[g][3], qscale, ma.y);
        }
        float mx0 = -1e30f, mx1 = -1e30f;
#pragma unroll
        for (int g = 0; g < 8; g++) {
            mx0 = fmaxf(mx0, fmaxf(s[g][0], s[g][1]));
            mx1 = fmaxf(mx1, fmaxf(s[g][2], s[g][3]));
        }
        mx0 = fmaxf(mx0, __shfl_xor_sync(0xffffffffu, mx0, 1));
        mx0 = fmaxf(mx0, __shfl_xor_sync(0xffffffffu, mx0, 2));
        mx1 = fmaxf(mx1, __shfl_xor_sync(0xffffffffu, mx1, 1));
        mx1 = fmaxf(mx1, __shfl_xor_sync(0xffffffffu, mx1, 2));
        float mn0 = fmaxf(m_i[0], mx0);
        float mn1 = fmaxf(m_i[1], mx1);
        float corr0 = exp2f(m_i[0] - mn0);
        float corr1 = exp2f(m_i[1] - mn1);
        m_i[0] = mn0; m_i[1] = mn1;

        uint32_t pah[4][4], pal[4][4];
        float sum0 = 0.0f, sum1 = 0.0f;
#pragma unroll
        for (int g = 0; g < 8; g++) {
            float p0 = exp2f(s[g][0] - mn0);
            float p1 = exp2f(s[g][1] - mn0);
            float p2 = exp2f(s[g][2] - mn1);
            float p3 = exp2f(s[g][3] - mn1);
            sum0 += p0 + p1;
            sum1 += p2 + p3;
            const int kc = g >> 1;
            const int o2 = (g & 1) * 2;
            pah[kc][o2 + 0] = pack_bf16x2(p0, p1);
            pah[kc][o2 + 1] = pack_bf16x2(p2, p3);
            pal[kc][o2 + 0] = pack_bf16x2(bf16_residual(p0), bf16_residual(p1));
            pal[kc][o2 + 1] = pack_bf16x2(bf16_residual(p2), bf16_residual(p3));
        }
        sum0 += __shfl_xor_sync(0xffffffffu, sum0, 1);
        sum0 += __shfl_xor_sync(0xffffffffu, sum0, 2);
        sum1 += __shfl_xor_sync(0xffffffffu, sum1, 1);
        sum1 += __shfl_xor_sync(0xffffffffu, sum1, 2);
        l_i[0] = l_i[0] * corr0 + sum0;
        l_i[1] = l_i[1] * corr1 + sum1;
#pragma unroll
        for (int g = 0; g < 8; g++) {
            o[g][0] *= corr0; o[g][1] *= corr0;
            o[g][2] *= corr1; o[g][3] *= corr1;
        }

#pragma unroll
        for (int kc = 0; kc < 4; kc++) {
            const int cb = tc4 + kc * 32;
#pragma unroll
            for (int db = 0; db < 2; db++) {
                uint32_t bh[4][2], bl[4][2];
#pragma unroll
                for (int j = 0; j < 4; j++) {
                    int bbase = ((db * 4 + j) * 8 + group) * ASHB + cb;
                    bh[j][0] = *(const uint32_t*)(pVh + bbase);
                    bh[j][1] = *(const uint32_t*)(pVh + bbase + 16);
                    bl[j][0] = *(const uint32_t*)(pVl + bbase);
                    bl[j][1] = *(const uint32_t*)(pVl + bbase + 16);
                }
#pragma unroll
                for (int j = 0; j < 4; j++)
                    mma_bf16(o[db * 4 + j], pah[kc], bh[j]);
#pragma unroll
                for (int j = 0; j < 4; j++)
                    mma_bf16(o[db * 4 + j], pah[kc], bl[j]);
#pragma unroll
                for (int j = 0; j < 4; j++)
                    mma_bf16(o[db * 4 + j], pal[kc], bh[j]);
            }
        }
        __syncthreads();

        if (kb + 2 < NT)
            attn_load_stage(sbase, kh, kl, vth, vtl, mk, b, hcol, kb + 2, t);
    }

    float inv0 = 1.0f / l_i[0];
    float inv1 = 1.0f / l_i[1];
    const int gr0 = qBase + w * 16 + group;
#pragma unroll
    for (int g = 0; g < 8; g++) {
        int col = hcol + g * 8 + (lane & 3) * 2;
        float v0 = o[g][0] * inv0, v1 = o[g][1] * inv0;
        float v2 = o[g][2] * inv1, v3 = o[g][3] * inv1;
        *reinterpret_cast<uint32_t*>(&Oh[(size_t)gr0 * DIM + col]) =
            pack_bf16x2(v0, v1);
        *reinterpret_cast<uint32_t*>(&Ol[(size_t)gr0 * DIM + col]) =
            pack_bf16x2(bf16_residual(v0), bf16_residual(v1));
        *reinterpret_cast<uint32_t*>(&Oh[(size_t)(gr0 + 8) * DIM + col]) =
            pack_bf16x2(v2, v3);
        *reinterpret_cast<uint32_t*>(&Ol[(size_t)(gr0 + 8) * DIM + col]) =
            pack_bf16x2(bf16_residual(v2), bf16_residual(v3));
    }
}

// ---------------------------------------------------------------------------
// Launcher. Capture slot = user-launch idx 3 (stable R10-R15):
//   0: prep  1: qkvGemm  2: transpose_v  3: attn <- capture  4: gemmO
// ---------------------------------------------------------------------------
extern "C" void kernel_launch(void* const* d_in, const int* in_sizes, int n_in,
                              void* d_out, int out_size) {
    (void)in_sizes; (void)n_in; (void)out_size;
    const float* x          = (const float*)d_in[0];
    const unsigned char* mk = (const unsigned char*)d_in[1];
    const float* w0 = (const float*)d_in[2];
    const float* w1 = (const float*)d_in[4];
    const float* w2 = (const float*)d_in[6];
    const float* w3 = (const float*)d_in[8];
    const float* bq = (const float*)d_in[3];
    const float* bk = (const float*)d_in[5];
    const float* bv = (const float*)d_in[7];
    const float* bo = (const float*)d_in[9];
    float* out = (float*)d_out;

    __nv_bfloat16 *xh, *xl, *qhp, *qlp, *khp, *klp, *vhp, *vlp;
    __nv_bfloat16 *vth, *vtl, *ah, *al, *wth, *wtl;
    cudaGetSymbolAddress((void**)&xh, g_x_hi);
    cudaGetSymbolAddress((void**)&xl, g_x_lo);
    cudaGetSymbolAddress((void**)&qhp, g_q_hi);
    cudaGetSymbolAddress((void**)&qlp, g_q_lo);
    cudaGetSymbolAddress((void**)&khp, g_k_hi);
    cudaGetSymbolAddress((void**)&klp, g_k_lo);
    cudaGetSymbolAddress((void**)&vhp, g_v_hi);
    cudaGetSymbolAddress((void**)&vlp, g_v_lo);
    cudaGetSymbolAddress((void**)&vth, g_vt_hi);
    cudaGetSymbolAddress((void**)&vtl, g_vt_lo);
    cudaGetSymbolAddress((void**)&ah, g_a_hi);
    cudaGetSymbolAddress((void**)&al, g_a_lo);
    cudaGetSymbolAddress((void**)&wth, g_wt_hi);
    cudaGetSymbolAddress((void**)&wtl, g_wt_lo);

    cudaFuncSetAttribute(qkv_gemm_kernel,
                         cudaFuncAttributeMaxDynamicSharedMemorySize, GEMM_SMEM);
    cudaFuncSetAttribute(out_gemm_kernel,
                         cudaFuncAttributeMaxDynamicSharedMemorySize, GEMM_SMEM);
    cudaFuncSetAttribute(attn_mma_kernel,
                         cudaFuncAttributeMaxDynamicSharedMemorySize, ATTN_SMEM);

    // idx 0: merged prep (x split + 4 weight transpose+splits)
    prep_kernel<<<8192, 256>>>(x, w0, w1, w2, w3, xh, xl, wth, wtl);
    // idx 1: merged persistent QKV GEMM
    qkv_gemm_kernel<<<2 * NSM, 256, GEMM_SMEM>>>(
        xh, xl, wth, wtl, bq, bk, bv, qhp, qlp, khp, klp, vhp, vlp);
    // idx 2: V transpose
    transpose_v_kernel<<<dim3(32, 32, 4), dim3(32, 8)>>>(vhp, vlp, vth, vtl);
    // idx 3: attention  <-- ncu capture target
    attn_mma_kernel<<<dim3(SLEN / ATQ, NH, 4), 256, ATTN_SMEM>>>(
        qhp, qlp, khp, klp, vth, vtl, mk, ah, al);
    // idx 4: output GEMM
    out_gemm_kernel<<<dim3(DIM / BN, M_ROWS / BM), 256, GEMM_SMEM>>>(
        ah, al, wth + 3 * (size_t)DIM * DIM, wtl + 3 * (size_t)DIM * DIM, bo, out);
}